// round 1
// baseline (speedup 1.0000x reference)
#include <cuda_runtime.h>

// ---------------------------------------------------------------------------
// CapsNet forward, fully fused:
//   conv(3x3, pad1) -> squash(len 8) -> priors einsum -> 3-iter dynamic routing
// Inputs (metadata order): x[16384,1,3,3] f32, conv_w[32,1,3,3] f32,
//                          lin_w[10,36,16,8] f32.  Output: [16384,10,16] f32.
//
// One block = 8 samples, 320 threads (2 groups x 160 "od" threads, od=o*16+d).
// priors kept entirely in SMEM (pitch-padded), routing fused, output written
// straight from registers. Weights pre-transposed to Wt[i][l][od] for
// coalesced 128B loads reused across all 8 samples in registers.
// ---------------------------------------------------------------------------

#define NS 8
#define PRIOR_PITCH 164          // 160 + 4 pad: conflict-free agreement reads

__device__ float g_wt[36 * 8 * 160];   // Wt[i][l][od]

__global__ void transpose_w_kernel(const float* __restrict__ lin_w) {
    int t = blockIdx.x * 256 + threadIdx.x;
    if (t >= 46080) return;
    int od = t % 160;
    int il = t / 160;
    int l = il % 8;
    int i = il / 8;
    int o = od / 16;
    int d = od % 16;
    // lin_w[o][i][d][l]
    g_wt[t] = lin_w[((o * 36 + i) * 16 + d) * 8 + l];
}

__global__ __launch_bounds__(320, 1)
void capsnet_kernel(const float* __restrict__ x,
                    const float* __restrict__ conv_w,
                    float* __restrict__ out_g) {
    extern __shared__ float sm[];
    float* s_priors = sm;                              // 8*36*164 = 47232 f
    float* s_caps   = s_priors + NS * 36 * PRIOR_PITCH; // 8*36*8   = 2304 f
    float* s_logit  = s_caps + NS * 36 * 8;            // 8*36*10  = 2880 f
    float* s_probs  = s_logit + NS * 360;              // 2880 f
    float* s_out    = s_probs + NS * 360;              // 8*160    = 1280 f
    float* s_x      = s_out + NS * 160;                // 72 f
    float* s_cw     = s_x + NS * 9;                    // 288 f

    const int tid = threadIdx.x;
    const int sample0 = blockIdx.x * NS;

    // ---- load inputs ----
    if (tid < NS * 9)  s_x[tid]  = x[sample0 * 9 + tid];
    if (tid < 288)     s_cw[tid] = conv_w[tid];
    __syncthreads();

    // ---- conv 3x3 pad1 on 3x3 input, write into capsule layout ----
    // task idx -> (s, c, h, w); caps index i = (h*3+w)*4 + (c/8), l = c%8
    for (int idx = tid; idx < NS * 288; idx += 320) {
        int s = idx / 288, r = idx % 288;
        int c = r / 9, p = r % 9;
        int h = p / 3, w = p % 3;
        float acc = 0.f;
        #pragma unroll
        for (int kh = 0; kh < 3; kh++) {
            int ih = h + kh - 1;
            if (ih < 0 || ih > 2) continue;
            #pragma unroll
            for (int kw = 0; kw < 3; kw++) {
                int iw = w + kw - 1;
                if (iw < 0 || iw > 2) continue;
                acc = fmaf(s_x[s * 9 + ih * 3 + iw], s_cw[c * 9 + kh * 3 + kw], acc);
            }
        }
        int g = c >> 3, l = c & 7;
        int i = p * 4 + g;
        s_caps[(s * 36 + i) * 8 + l] = acc;
    }
    __syncthreads();

    // ---- squash capsules over length 8 ----
    for (int idx = tid; idx < NS * 36; idx += 320) {
        float* cp = &s_caps[idx * 8];
        float n2 = 0.f;
        #pragma unroll
        for (int l = 0; l < 8; l++) n2 = fmaf(cp[l], cp[l], n2);
        float f = n2 / (1.f + n2) * rsqrtf(n2 + 1e-8f);
        #pragma unroll
        for (int l = 0; l < 8; l++) cp[l] *= f;
    }
    __syncthreads();

    // ---- priors: priors[s][i][od] = sum_l Wt[i][l][od] * caps[s][i][l] ----
    const int grp = tid / 160;       // 0 or 1 : i-range split
    const int od  = tid % 160;
    {
        const int i0 = grp * 18;
        #pragma unroll 2
        for (int ii = 0; ii < 18; ii++) {
            const int i = i0 + ii;
            float w0 = __ldg(&g_wt[(i * 8 + 0) * 160 + od]);
            float w1 = __ldg(&g_wt[(i * 8 + 1) * 160 + od]);
            float w2 = __ldg(&g_wt[(i * 8 + 2) * 160 + od]);
            float w3 = __ldg(&g_wt[(i * 8 + 3) * 160 + od]);
            float w4 = __ldg(&g_wt[(i * 8 + 4) * 160 + od]);
            float w5 = __ldg(&g_wt[(i * 8 + 5) * 160 + od]);
            float w6 = __ldg(&g_wt[(i * 8 + 6) * 160 + od]);
            float w7 = __ldg(&g_wt[(i * 8 + 7) * 160 + od]);
            #pragma unroll
            for (int s = 0; s < NS; s++) {
                const float4* cp = (const float4*)&s_caps[(s * 36 + i) * 8];
                float4 a = cp[0], b = cp[1];
                float acc;
                acc = w0 * a.x;
                acc = fmaf(w1, a.y, acc);
                acc = fmaf(w2, a.z, acc);
                acc = fmaf(w3, a.w, acc);
                acc = fmaf(w4, b.x, acc);
                acc = fmaf(w5, b.y, acc);
                acc = fmaf(w6, b.z, acc);
                acc = fmaf(w7, b.w, acc);
                s_priors[(s * 36 + i) * PRIOR_PITCH + od] = acc;
            }
        }
    }
    __syncthreads();

    // ---- dynamic routing (3 iterations) ----
    const int o = od / 16;
    const unsigned FULL = 0xffffffffu;
    const int sOff = grp * 4;        // this thread covers samples sOff..sOff+3
    float outr[4];

    for (int it = 0; it < 3; it++) {
        if (it > 0) {
            __syncthreads();   // agreement wrote s_logit
            // softmax over o, per (s,i)
            for (int idx = tid; idx < NS * 36; idx += 320) {
                const float* lg = &s_logit[idx * 10];
                float m = lg[0];
                #pragma unroll
                for (int oo = 1; oo < 10; oo++) m = fmaxf(m, lg[oo]);
                float e[10];
                float sum = 0.f;
                #pragma unroll
                for (int oo = 0; oo < 10; oo++) { e[oo] = __expf(lg[oo] - m); sum += e[oo]; }
                float inv = 1.f / sum;
                float* pb = &s_probs[idx * 10];
                #pragma unroll
                for (int oo = 0; oo < 10; oo++) pb[oo] = e[oo] * inv;
            }
            __syncthreads();
        }

        // weighted sum over i + squash over d (16-lane shfl groups)
        #pragma unroll
        for (int ss = 0; ss < 4; ss++) {
            const int s = sOff + ss;
            float acc = 0.f;
            if (it == 0) {
                for (int i = 0; i < 36; i++)
                    acc += s_priors[(s * 36 + i) * PRIOR_PITCH + od];
                acc *= 0.1f;   // softmax(0) over 10 classes
            } else {
                for (int i = 0; i < 36; i++)
                    acc = fmaf(s_probs[(s * 36 + i) * 10 + o],
                               s_priors[(s * 36 + i) * PRIOR_PITCH + od], acc);
            }
            float n2 = acc * acc;
            n2 += __shfl_xor_sync(FULL, n2, 1);
            n2 += __shfl_xor_sync(FULL, n2, 2);
            n2 += __shfl_xor_sync(FULL, n2, 4);
            n2 += __shfl_xor_sync(FULL, n2, 8);
            float f = n2 / (1.f + n2) * rsqrtf(n2 + 1e-8f);
            outr[ss] = acc * f;
        }

        if (it == 2) break;

        // publish out, then agreement: logits[s][i][o] (+)= sum_d priors*out
        #pragma unroll
        for (int ss = 0; ss < 4; ss++)
            s_out[(sOff + ss) * 160 + od] = outr[ss];
        __syncthreads();

        for (int t = tid; t < NS * 360; t += 320) {
            int s = t / 360;
            int r = t % 360;
            int oo = r / 36;
            int i = r % 36;
            const float* pr = &s_priors[(s * 36 + i) * PRIOR_PITCH + oo * 16];
            const float* ov = &s_out[s * 160 + oo * 16];
            float sum = 0.f;
            #pragma unroll
            for (int dd = 0; dd < 16; dd++) sum = fmaf(pr[dd], ov[dd], sum);
            float* lp = &s_logit[(s * 36 + i) * 10 + oo];
            if (it == 0) *lp = sum;    // initial logits are zero
            else         *lp += sum;
        }
        // sync handled at top of next iteration
    }

    // ---- write output ----
    #pragma unroll
    for (int ss = 0; ss < 4; ss++)
        out_g[(sample0 + sOff + ss) * 160 + od] = outr[ss];
}

extern "C" void kernel_launch(void* const* d_in, const int* in_sizes, int n_in,
                              void* d_out, int out_size) {
    const float* x      = (const float*)d_in[0];
    const float* conv_w = (const float*)d_in[1];
    const float* lin_w  = (const float*)d_in[2];
    float* out = (float*)d_out;

    transpose_w_kernel<<<(46080 + 255) / 256, 256>>>(lin_w);

    size_t smem_f = (size_t)NS * 36 * PRIOR_PITCH + NS * 36 * 8
                  + NS * 360 * 2 + NS * 160 + NS * 9 + 288;
    size_t smem_bytes = smem_f * sizeof(float);
    cudaFuncSetAttribute(capsnet_kernel,
                         cudaFuncAttributeMaxDynamicSharedMemorySize,
                         (int)smem_bytes);

    int blocks = 16384 / NS;   // 2048
    capsnet_kernel<<<blocks, 320, smem_bytes>>>(x, conv_w, out);
}

// round 4
// speedup vs baseline: 1.0825x; 1.0825x over previous
#include <cuda_runtime.h>

// ---------------------------------------------------------------------------
// CapsNet forward, fully fused:
//   conv(3x3, pad1) -> squash(len 8) -> priors einsum -> 3-iter dynamic routing
// Inputs: x[16384,1,3,3] f32, conv_w[32,1,3,3] f32, lin_w[10,36,16,8] f32.
// Output: [16384,10,16] f32.
//
// One block = 8 samples, 1024 threads (32 warps -> 50% occ).
// priors in SMEM with pitch 161 (161 mod 32 = 1 -> conflict-free strided
// reads) -- pitch reduced from 165 so total smem (226,592 B) stays BELOW the
// R1-proven 227,744 B, de-risking the suspected smem-limit container kill.
// logits/probs padded to stride 11 (coprime to 32).
// ---------------------------------------------------------------------------

#define NS 8
#define PRIOR_PITCH 161     // 161 mod 32 = 1 -> conflict-free
#define LPITCH 11           // logits/probs pitch (gcd(11,32)=1)
#define NTHR 1024

__device__ float g_wt[36 * 8 * 160];   // Wt[i][l][od]

__global__ void transpose_w_kernel(const float* __restrict__ lin_w) {
    int t = blockIdx.x * 256 + threadIdx.x;
    if (t >= 46080) return;
    int od = t % 160;
    int il = t / 160;
    int l = il % 8;
    int i = il / 8;
    int o = od / 16;
    int d = od % 16;
    g_wt[t] = lin_w[((o * 36 + i) * 16 + d) * 8 + l];   // lin_w[o][i][d][l]
}

__global__ __launch_bounds__(NTHR, 1)
void capsnet_kernel(const float* __restrict__ x,
                    const float* __restrict__ conv_w,
                    float* __restrict__ out_g) {
    extern __shared__ float sm[];
    float* s_priors = sm;                               // 8*36*161 = 46368 f
    float* s_caps   = s_priors + NS * 36 * PRIOR_PITCH; // 8*36*8   = 2304 f
    float* s_logit  = s_caps + NS * 36 * 8;             // 8*36*11  = 3168 f
    float* s_probs  = s_logit + NS * 36 * LPITCH;       // 3168 f
    float* s_out    = s_probs + NS * 36 * LPITCH;       // 8*160    = 1280 f
    float* s_x      = s_out + NS * 160;                 // 72 f
    float* s_cw     = s_x + NS * 9;                     // 288 f

    const int tid = threadIdx.x;
    const int sample0 = blockIdx.x * NS;

    // ---- load inputs ----
    if (tid < NS * 9)  s_x[tid]  = x[sample0 * 9 + tid];
    else if (tid >= 128 && tid < 128 + 288) s_cw[tid - 128] = conv_w[tid - 128];
    __syncthreads();

    // ---- conv 3x3 pad1 on 3x3 input, write into capsule layout ----
    for (int idx = tid; idx < NS * 288; idx += NTHR) {
        int s = idx / 288, r = idx % 288;
        int c = r / 9, p = r % 9;
        int h = p / 3, w = p % 3;
        float acc = 0.f;
        #pragma unroll
        for (int kh = 0; kh < 3; kh++) {
            int ih = h + kh - 1;
            if (ih < 0 || ih > 2) continue;
            #pragma unroll
            for (int kw = 0; kw < 3; kw++) {
                int iw = w + kw - 1;
                if (iw < 0 || iw > 2) continue;
                acc = fmaf(s_x[s * 9 + ih * 3 + iw], s_cw[c * 9 + kh * 3 + kw], acc);
            }
        }
        int g = c >> 3, l = c & 7;
        int i = p * 4 + g;
        s_caps[(s * 36 + i) * 8 + l] = acc;
    }
    __syncthreads();

    // ---- squash capsules over length 8 ----
    if (tid < NS * 36) {
        float* cp = &s_caps[tid * 8];
        float n2 = 0.f;
        #pragma unroll
        for (int l = 0; l < 8; l++) n2 = fmaf(cp[l], cp[l], n2);
        float f = n2 / (1.f + n2) * rsqrtf(n2 + 1e-8f);
        #pragma unroll
        for (int l = 0; l < 8; l++) cp[l] *= f;
    }
    __syncthreads();

    // ---- priors: priors[s][i][od] = sum_l Wt[i][l][od] * caps[s][i][l] ----
    // task = (i, od); each task serves all 8 samples from registers.
    for (int t = tid; t < 36 * 160; t += NTHR) {
        const int od = t % 160;
        const int i  = t / 160;
        const float* wp = &g_wt[i * 8 * 160 + od];
        float w0 = wp[0 * 160], w1 = wp[1 * 160], w2 = wp[2 * 160], w3 = wp[3 * 160];
        float w4 = wp[4 * 160], w5 = wp[5 * 160], w6 = wp[6 * 160], w7 = wp[7 * 160];
        #pragma unroll
        for (int s = 0; s < NS; s++) {
            const float4* cp = (const float4*)&s_caps[(s * 36 + i) * 8];
            float4 a = cp[0], b = cp[1];
            float acc;
            acc = w0 * a.x;
            acc = fmaf(w1, a.y, acc);
            acc = fmaf(w2, a.z, acc);
            acc = fmaf(w3, a.w, acc);
            acc = fmaf(w4, b.x, acc);
            acc = fmaf(w5, b.y, acc);
            acc = fmaf(w6, b.z, acc);
            acc = fmaf(w7, b.w, acc);
            s_priors[(s * 36 + i) * PRIOR_PITCH + od] = acc;
        }
    }
    __syncthreads();

    // ---- dynamic routing (3 iterations) ----
    const unsigned FULL = 0xffffffffu;
    float outr[2];                 // up to 2 (s,od) tasks per thread

    for (int it = 0; it < 3; it++) {
        if (it > 0) {
            __syncthreads();       // agreement wrote s_logit
            if (tid < NS * 36) {   // softmax over o, per (s,i)
                const float* lg = &s_logit[tid * LPITCH];
                float m = lg[0];
                #pragma unroll
                for (int oo = 1; oo < 10; oo++) m = fmaxf(m, lg[oo]);
                float e[10];
                float sum = 0.f;
                #pragma unroll
                for (int oo = 0; oo < 10; oo++) { e[oo] = __expf(lg[oo] - m); sum += e[oo]; }
                float inv = 1.f / sum;
                float* pb = &s_probs[tid * LPITCH];
                #pragma unroll
                for (int oo = 0; oo < 10; oo++) pb[oo] = e[oo] * inv;
            }
            __syncthreads();
        }

        // weighted sum over i + squash over d (16-lane shfl groups).
        // tasks t in [0,1280): s = t/160, od = t%160. Pass 2 covers tid<256
        // (whole warps only, so full-mask shfl is safe; 16-aligned offsets
        // keep each shfl group on a single (s,o)).
        #pragma unroll
        for (int p = 0; p < 2; p++) {
            const int t = tid + p * NTHR;
            if (t >= NS * 160) break;
            const int s = t / 160, od = t % 160, o = od / 16;
            float acc = 0.f;
            if (it == 0) {
                const float* pr = &s_priors[s * 36 * PRIOR_PITCH + od];
                #pragma unroll 4
                for (int i = 0; i < 36; i++) acc += pr[i * PRIOR_PITCH];
                acc *= 0.1f;                       // softmax(0) over 10 classes
            } else {
                const float* pr = &s_priors[s * 36 * PRIOR_PITCH + od];
                const float* pb = &s_probs[s * 36 * LPITCH + o];
                #pragma unroll 4
                for (int i = 0; i < 36; i++)
                    acc = fmaf(pb[i * LPITCH], pr[i * PRIOR_PITCH], acc);
            }
            float n2 = acc * acc;
            n2 += __shfl_xor_sync(FULL, n2, 1);
            n2 += __shfl_xor_sync(FULL, n2, 2);
            n2 += __shfl_xor_sync(FULL, n2, 4);
            n2 += __shfl_xor_sync(FULL, n2, 8);
            float f = n2 / (1.f + n2) * rsqrtf(n2 + 1e-8f);
            outr[p] = acc * f;
            if (it < 2) s_out[s * 160 + od] = outr[p];
        }

        if (it == 2) break;
        __syncthreads();           // s_out published

        // agreement: logits[s][i][o] (+)= sum_d priors[s][i][o*16+d]*out[s][o*16+d]
        for (int t = tid; t < NS * 360; t += NTHR) {
            int s = t / 360;
            int r = t % 360;
            int oo = r / 36;
            int i = r % 36;
            const float* pr = &s_priors[(s * 36 + i) * PRIOR_PITCH + oo * 16];
            const float* ov = &s_out[s * 160 + oo * 16];
            float sum = 0.f;
            #pragma unroll
            for (int dd = 0; dd < 16; dd++) sum = fmaf(pr[dd], ov[dd], sum);
            float* lp = &s_logit[(s * 36 + i) * LPITCH + oo];
            if (it == 0) *lp = sum;    // initial logits are zero
            else         *lp += sum;
        }
        // sync handled at top of next iteration
    }

    // ---- write output ----
    #pragma unroll
    for (int p = 0; p < 2; p++) {
        const int t = tid + p * NTHR;
        if (t >= NS * 160) break;
        out_g[sample0 * 160 + t] = outr[p];
    }
}

extern "C" void kernel_launch(void* const* d_in, const int* in_sizes, int n_in,
                              void* d_out, int out_size) {
    const float* x      = (const float*)d_in[0];
    const float* conv_w = (const float*)d_in[1];
    const float* lin_w  = (const float*)d_in[2];
    float* out = (float*)d_out;

    transpose_w_kernel<<<(46080 + 255) / 256, 256>>>(lin_w);

    size_t smem_f = (size_t)NS * 36 * PRIOR_PITCH + NS * 36 * 8
                  + (size_t)NS * 36 * LPITCH * 2 + NS * 160 + NS * 9 + 288;
    size_t smem_bytes = smem_f * sizeof(float);   // 226,592 B (< R1's 227,744)
    cudaFuncSetAttribute(capsnet_kernel,
                         cudaFuncAttributeMaxDynamicSharedMemorySize,
                         (int)smem_bytes);

    int blocks = 16384 / NS;   // 2048
    capsnet_kernel<<<blocks, NTHR, smem_bytes>>>(x, conv_w, out);
}

// round 5
// speedup vs baseline: 1.2281x; 1.1345x over previous
#include <cuda_runtime.h>

// ---------------------------------------------------------------------------
// CapsNet forward, fully fused:
//   conv(3x3, pad1) -> squash(len 8) -> priors einsum -> 3-iter dynamic routing
// Inputs: x[16384,1,3,3] f32, conv_w[32,1,3,3] f32, lin_w[10,36,16,8] f32.
// Output: [16384,10,16] f32.
//
// One block = 8 samples, 1024 threads. LSU-wavefront optimized:
//  - PRIOR_PITCH=164: rows 16B-aligned, lane-stride-164 LDS.128 tiles banks
//    perfectly (164 mod 32 = 4) -> agreement pass reads priors+out as float4
//    (9 wavefronts/task instead of 33).
//  - probs stored transposed [s][o][i] (pitch 36, 16B-aligned rows) ->
//    weighted-sum reads probs as 9x LDS.128 broadcast instead of 36 scalar.
//  - total smem = 227,744 B (exactly the R1-proven size).
// ---------------------------------------------------------------------------

#define NS 8
#define PRIOR_PITCH 164     // mod 32 = 4 -> conflict-free .128 lane tiling; 16B rows
#define LPITCH 10           // logits pitch
#define PPITCH 36           // probs_t pitch: [s][o][i], rows 144B (16B-aligned)
#define NTHR 1024

__device__ float g_wt[36 * 8 * 160];   // Wt[i][l][od]

__global__ void transpose_w_kernel(const float* __restrict__ lin_w) {
    int t = blockIdx.x * 256 + threadIdx.x;
    if (t >= 46080) return;
    int od = t % 160;
    int il = t / 160;
    int l = il % 8;
    int i = il / 8;
    int o = od / 16;
    int d = od % 16;
    g_wt[t] = lin_w[((o * 36 + i) * 16 + d) * 8 + l];   // lin_w[o][i][d][l]
}

__global__ __launch_bounds__(NTHR, 1)
void capsnet_kernel(const float* __restrict__ x,
                    const float* __restrict__ conv_w,
                    float* __restrict__ out_g) {
    extern __shared__ float sm[];
    float* s_priors = sm;                               // 8*36*164 = 47232 f
    float* s_caps   = s_priors + NS * 36 * PRIOR_PITCH; // 2304 f
    float* s_logit  = s_caps + NS * 36 * 8;             // 8*36*10 = 2880 f
    float* s_probst = s_logit + NS * 36 * LPITCH;       // 8*10*36 = 2880 f
    float* s_out    = s_probst + NS * 10 * PPITCH;      // 1280 f (16B-aligned)
    float* s_x      = s_out + NS * 160;                 // 72 f
    float* s_cw     = s_x + NS * 9;                     // 288 f
    // total = 56936 floats = 227,744 B

    const int tid = threadIdx.x;
    const int sample0 = blockIdx.x * NS;

    // ---- load inputs ----
    if (tid < NS * 9)  s_x[tid]  = x[sample0 * 9 + tid];
    else if (tid >= 128 && tid < 128 + 288) s_cw[tid - 128] = conv_w[tid - 128];
    __syncthreads();

    // ---- conv 3x3 pad1 on 3x3 input, write into capsule layout ----
    for (int idx = tid; idx < NS * 288; idx += NTHR) {
        int s = idx / 288, r = idx % 288;
        int c = r / 9, p = r % 9;
        int h = p / 3, w = p % 3;
        float acc = 0.f;
        #pragma unroll
        for (int kh = 0; kh < 3; kh++) {
            int ih = h + kh - 1;
            if (ih < 0 || ih > 2) continue;
            #pragma unroll
            for (int kw = 0; kw < 3; kw++) {
                int iw = w + kw - 1;
                if (iw < 0 || iw > 2) continue;
                acc = fmaf(s_x[s * 9 + ih * 3 + iw], s_cw[c * 9 + kh * 3 + kw], acc);
            }
        }
        int g = c >> 3, l = c & 7;
        int i = p * 4 + g;
        s_caps[(s * 36 + i) * 8 + l] = acc;
    }
    __syncthreads();

    // ---- squash capsules over length 8 ----
    if (tid < NS * 36) {
        float* cp = &s_caps[tid * 8];
        float n2 = 0.f;
        #pragma unroll
        for (int l = 0; l < 8; l++) n2 = fmaf(cp[l], cp[l], n2);
        float f = n2 / (1.f + n2) * rsqrtf(n2 + 1e-8f);
        #pragma unroll
        for (int l = 0; l < 8; l++) cp[l] *= f;
    }
    __syncthreads();

    // ---- priors: priors[s][i][od] = sum_l Wt[i][l][od] * caps[s][i][l] ----
    for (int t = tid; t < 36 * 160; t += NTHR) {
        const int od = t % 160;
        const int i  = t / 160;
        const float* wp = &g_wt[i * 8 * 160 + od];
        float w0 = wp[0 * 160], w1 = wp[1 * 160], w2 = wp[2 * 160], w3 = wp[3 * 160];
        float w4 = wp[4 * 160], w5 = wp[5 * 160], w6 = wp[6 * 160], w7 = wp[7 * 160];
        #pragma unroll
        for (int s = 0; s < NS; s++) {
            const float4* cp = (const float4*)&s_caps[(s * 36 + i) * 8];
            float4 a = cp[0], b = cp[1];
            float acc;
            acc = w0 * a.x;
            acc = fmaf(w1, a.y, acc);
            acc = fmaf(w2, a.z, acc);
            acc = fmaf(w3, a.w, acc);
            acc = fmaf(w4, b.x, acc);
            acc = fmaf(w5, b.y, acc);
            acc = fmaf(w6, b.z, acc);
            acc = fmaf(w7, b.w, acc);
            s_priors[(s * 36 + i) * PRIOR_PITCH + od] = acc;
        }
    }
    __syncthreads();

    // ---- dynamic routing (3 iterations) ----
    const unsigned FULL = 0xffffffffu;
    float outr[2];                 // up to 2 (s,od) tasks per thread

    for (int it = 0; it < 3; it++) {
        if (it > 0) {
            __syncthreads();       // agreement wrote s_logit
            if (tid < NS * 36) {   // softmax over o, per (s,i) -> probs_t[s][o][i]
                const int s = tid / 36, i = tid % 36;
                const float* lg = &s_logit[tid * LPITCH];
                float m = lg[0];
                #pragma unroll
                for (int oo = 1; oo < 10; oo++) m = fmaxf(m, lg[oo]);
                float e[10];
                float sum = 0.f;
                #pragma unroll
                for (int oo = 0; oo < 10; oo++) { e[oo] = __expf(lg[oo] - m); sum += e[oo]; }
                float inv = 1.f / sum;
                #pragma unroll
                for (int oo = 0; oo < 10; oo++)
                    s_probst[(s * 10 + oo) * PPITCH + i] = e[oo] * inv;
            }
            __syncthreads();
        }

        // weighted sum over i + squash over d (16-lane shfl groups).
        // tasks t in [0,1280): s = t/160, od = t%160. Pass 2 covers tid<256
        // (whole warps; 16-aligned offsets keep shfl groups on one (s,o)).
        #pragma unroll
        for (int p = 0; p < 2; p++) {
            const int t = tid + p * NTHR;
            if (t >= NS * 160) break;
            const int s = t / 160, od = t % 160, o = od / 16;
            float acc = 0.f;
            const float* pr = &s_priors[s * 36 * PRIOR_PITCH + od];
            if (it == 0) {
                #pragma unroll 4
                for (int i = 0; i < 36; i++) acc += pr[i * PRIOR_PITCH];
                acc *= 0.1f;                       // softmax(0) over 10 classes
            } else {
                const float4* pb4 = (const float4*)&s_probst[(s * 10 + o) * PPITCH];
                #pragma unroll
                for (int ii = 0; ii < 9; ii++) {
                    float4 pv = pb4[ii];
                    acc = fmaf(pv.x, pr[(4 * ii + 0) * PRIOR_PITCH], acc);
                    acc = fmaf(pv.y, pr[(4 * ii + 1) * PRIOR_PITCH], acc);
                    acc = fmaf(pv.z, pr[(4 * ii + 2) * PRIOR_PITCH], acc);
                    acc = fmaf(pv.w, pr[(4 * ii + 3) * PRIOR_PITCH], acc);
                }
            }
            float n2 = acc * acc;
            n2 += __shfl_xor_sync(FULL, n2, 1);
            n2 += __shfl_xor_sync(FULL, n2, 2);
            n2 += __shfl_xor_sync(FULL, n2, 4);
            n2 += __shfl_xor_sync(FULL, n2, 8);
            float f = n2 / (1.f + n2) * rsqrtf(n2 + 1e-8f);
            outr[p] = acc * f;
            if (it < 2) s_out[s * 160 + od] = outr[p];
        }

        if (it == 2) break;
        __syncthreads();           // s_out published

        // agreement: logits[s][i][o] (+)= sum_d priors[s][i][o*16+d]*out[s][o*16+d]
        // float4-vectorized: prior rows are 16B-aligned (pitch 164),
        // lane stride 164 words tiles banks perfectly for LDS.128.
        for (int t = tid; t < NS * 360; t += NTHR) {
            int s = t / 360;
            int r = t % 360;
            int oo = r / 36;
            int i = r % 36;
            const float4* pr4 = (const float4*)&s_priors[(s * 36 + i) * PRIOR_PITCH + oo * 16];
            const float4* ov4 = (const float4*)&s_out[s * 160 + oo * 16];
            float sum = 0.f;
            #pragma unroll
            for (int q = 0; q < 4; q++) {
                float4 a = pr4[q], b = ov4[q];
                sum = fmaf(a.x, b.x, sum);
                sum = fmaf(a.y, b.y, sum);
                sum = fmaf(a.z, b.z, sum);
                sum = fmaf(a.w, b.w, sum);
            }
            float* lp = &s_logit[(s * 36 + i) * LPITCH + oo];
            if (it == 0) *lp = sum;    // initial logits are zero
            else         *lp += sum;
        }
        // sync handled at top of next iteration
    }

    // ---- write output ----
    #pragma unroll
    for (int p = 0; p < 2; p++) {
        const int t = tid + p * NTHR;
        if (t >= NS * 160) break;
        out_g[sample0 * 160 + t] = outr[p];
    }
}

extern "C" void kernel_launch(void* const* d_in, const int* in_sizes, int n_in,
                              void* d_out, int out_size) {
    const float* x      = (const float*)d_in[0];
    const float* conv_w = (const float*)d_in[1];
    const float* lin_w  = (const float*)d_in[2];
    float* out = (float*)d_out;

    transpose_w_kernel<<<(46080 + 255) / 256, 256>>>(lin_w);

    size_t smem_f = (size_t)NS * 36 * PRIOR_PITCH + NS * 36 * 8
                  + (size_t)NS * 36 * LPITCH + (size_t)NS * 10 * PPITCH
                  + NS * 160 + NS * 9 + 288;
    size_t smem_bytes = smem_f * sizeof(float);   // 227,744 B (R1-proven size)
    cudaFuncSetAttribute(capsnet_kernel,
                         cudaFuncAttributeMaxDynamicSharedMemorySize,
                         (int)smem_bytes);

    int blocks = 16384 / NS;   // 2048
    capsnet_kernel<<<blocks, NTHR, smem_bytes>>>(x, conv_w, out);
}

// round 6
// speedup vs baseline: 1.6382x; 1.3340x over previous
#include <cuda_runtime.h>
#include <cuda_fp16.h>

// ---------------------------------------------------------------------------
// CapsNet forward, fully fused, fp16-priors edition.
//   conv(3x3,pad1) -> squash(8) -> priors einsum -> 3-iter dynamic routing
// Inputs: x[16384,1,3,3] f32, conv_w[32,1,3,3] f32, lin_w[10,36,16,8] f32.
// Output: [16384,10,16] f32.
//
// Key change vs R5: priors stored as half2 (pairs along od), all math fp32.
// Halves L1 crossbar bytes on the 6 priors passes (1 write + 5 reads), halves
// priors-phase task count (each task computes an od-pair via float2 weights).
// Pitch 84 half2 (336B rows): lane stride 84 words mod 32 = 20 -> 8-lane
// groups tile all 32 banks -> conflict-free uint4 reads in agreement.
// smem = 136,736 B, 1 CTA x 1024 threads.
// ---------------------------------------------------------------------------

#define NS 8
#define HP2PITCH 84         // half2 units per prior row (80 data + 4 pad)
#define LPITCH 11           // logits pitch (gcd(11,32)=1)
#define NTHR 1024

__device__ float g_wt[36 * 8 * 160];   // Wt[i][l][od]

__global__ void transpose_w_kernel(const float* __restrict__ lin_w) {
    int t = blockIdx.x * 256 + threadIdx.x;
    if (t >= 46080) return;
    int od = t % 160;
    int il = t / 160;
    int l = il % 8;
    int i = il / 8;
    int o = od / 16;
    int d = od % 16;
    g_wt[t] = lin_w[((o * 36 + i) * 16 + d) * 8 + l];   // lin_w[o][i][d][l]
}

__global__ __launch_bounds__(NTHR, 1)
void capsnet_kernel(const float* __restrict__ x,
                    const float* __restrict__ conv_w,
                    float* __restrict__ out_g) {
    extern __shared__ float sm[];
    __half2* ph     = (__half2*)sm;                     // 8*36*84 h2 = 24192 slots
    float* s_caps   = sm + NS * 36 * HP2PITCH;          // 2304 f
    float* s_probst = s_caps + NS * 36 * 8;             // 8*10*36 = 2880 f
    float* s_out    = s_probst + NS * 360;              // 8*160 = 1280 f
    float* s_logit  = s_out + NS * 160;                 // 8*36*11 = 3168 f
    float* s_x      = s_logit + NS * 36 * LPITCH;       // 72 f
    float* s_cw     = s_x + NS * 9;                     // 288 f
    // total = 34184 floats = 136,736 B

    const int tid = threadIdx.x;
    const int sample0 = blockIdx.x * NS;

    // ---- load inputs ----
    if (tid < NS * 9)  s_x[tid]  = x[sample0 * 9 + tid];
    else if (tid >= 128 && tid < 128 + 288) s_cw[tid - 128] = conv_w[tid - 128];
    __syncthreads();

    // ---- conv 3x3 pad1 on 3x3 input, into capsule layout ----
    for (int idx = tid; idx < NS * 288; idx += NTHR) {
        int s = idx / 288, r = idx % 288;
        int c = r / 9, p = r % 9;
        int h = p / 3, w = p % 3;
        float acc = 0.f;
        #pragma unroll
        for (int kh = 0; kh < 3; kh++) {
            int ih = h + kh - 1;
            if (ih < 0 || ih > 2) continue;
            #pragma unroll
            for (int kw = 0; kw < 3; kw++) {
                int iw = w + kw - 1;
                if (iw < 0 || iw > 2) continue;
                acc = fmaf(s_x[s * 9 + ih * 3 + iw], s_cw[c * 9 + kh * 3 + kw], acc);
            }
        }
        int g = c >> 3, l = c & 7;
        int i = p * 4 + g;
        s_caps[(s * 36 + i) * 8 + l] = acc;
    }
    __syncthreads();

    // ---- squash capsules over length 8 ----
    if (tid < NS * 36) {
        float* cp = &s_caps[tid * 8];
        float n2 = 0.f;
        #pragma unroll
        for (int l = 0; l < 8; l++) n2 = fmaf(cp[l], cp[l], n2);
        float f = n2 / (1.f + n2) * rsqrtf(n2 + 1e-8f);
        #pragma unroll
        for (int l = 0; l < 8; l++) cp[l] *= f;
    }
    __syncthreads();

    // ---- priors (half2 pairs): task = (i, od2); fp32 math, fp16 store ----
    for (int t = tid; t < 36 * 80; t += NTHR) {
        const int od2 = t % 80;
        const int i   = t / 80;
        const float2* wb = (const float2*)g_wt;
        float2 w0 = wb[(i * 8 + 0) * 80 + od2];
        float2 w1 = wb[(i * 8 + 1) * 80 + od2];
        float2 w2 = wb[(i * 8 + 2) * 80 + od2];
        float2 w3 = wb[(i * 8 + 3) * 80 + od2];
        float2 w4 = wb[(i * 8 + 4) * 80 + od2];
        float2 w5 = wb[(i * 8 + 5) * 80 + od2];
        float2 w6 = wb[(i * 8 + 6) * 80 + od2];
        float2 w7 = wb[(i * 8 + 7) * 80 + od2];
        #pragma unroll
        for (int s = 0; s < NS; s++) {
            const float4* cp = (const float4*)&s_caps[(s * 36 + i) * 8];
            float4 a = cp[0], b = cp[1];
            float a0 = w0.x * a.x, a1 = w0.y * a.x;
            a0 = fmaf(w1.x, a.y, a0); a1 = fmaf(w1.y, a.y, a1);
            a0 = fmaf(w2.x, a.z, a0); a1 = fmaf(w2.y, a.z, a1);
            a0 = fmaf(w3.x, a.w, a0); a1 = fmaf(w3.y, a.w, a1);
            a0 = fmaf(w4.x, b.x, a0); a1 = fmaf(w4.y, b.x, a1);
            a0 = fmaf(w5.x, b.y, a0); a1 = fmaf(w5.y, b.y, a1);
            a0 = fmaf(w6.x, b.z, a0); a1 = fmaf(w6.y, b.z, a1);
            a0 = fmaf(w7.x, b.w, a0); a1 = fmaf(w7.y, b.w, a1);
            ph[(s * 36 + i) * HP2PITCH + od2] = __floats2half2_rn(a0, a1);
        }
    }
    __syncthreads();

    // ---- dynamic routing (3 iterations) ----
    const unsigned FULL = 0xffffffffu;
    float out0 = 0.f, out1 = 0.f;
    const int s_ws   = tid / 80;       // ws task: (s, od2), tid < 640
    const int od2_ws = tid % 80;
    const int o_ws   = od2_ws / 8;

    for (int it = 0; it < 3; it++) {
        if (it > 0) {
            __syncthreads();           // agreement wrote s_logit
            if (tid < NS * 36) {       // softmax over o -> probs_t[s][o][i]
                const int s = tid / 36, i = tid % 36;
                const float* lg = &s_logit[tid * LPITCH];
                float m = lg[0];
                #pragma unroll
                for (int oo = 1; oo < 10; oo++) m = fmaxf(m, lg[oo]);
                float e[10];
                float sum = 0.f;
                #pragma unroll
                for (int oo = 0; oo < 10; oo++) { e[oo] = __expf(lg[oo] - m); sum += e[oo]; }
                float inv = 1.f / sum;
                #pragma unroll
                for (int oo = 0; oo < 10; oo++)
                    s_probst[(s * 10 + oo) * 36 + i] = e[oo] * inv;
            }
            __syncthreads();
        }

        // weighted sum over i + squash over d. 640 tasks (20 whole warps);
        // 8-lane shfl groups each hold one (s,o) with 2 d per lane.
        if (tid < NS * 80) {
            const __half2* pr = ph + s_ws * 36 * HP2PITCH + od2_ws;
            float acc0 = 0.f, acc1 = 0.f;
            if (it == 0) {
                #pragma unroll 4
                for (int i = 0; i < 36; i++) {
                    float2 p = __half22float2(pr[i * HP2PITCH]);
                    acc0 += p.x; acc1 += p.y;
                }
                acc0 *= 0.1f; acc1 *= 0.1f;    // softmax(0) over 10 classes
            } else {
                const float4* pb4 = (const float4*)&s_probst[(s_ws * 10 + o_ws) * 36];
                #pragma unroll
                for (int ii = 0; ii < 9; ii++) {
                    float4 pv = pb4[ii];
                    float2 p0 = __half22float2(pr[(4 * ii + 0) * HP2PITCH]);
                    float2 p1 = __half22float2(pr[(4 * ii + 1) * HP2PITCH]);
                    float2 p2 = __half22float2(pr[(4 * ii + 2) * HP2PITCH]);
                    float2 p3 = __half22float2(pr[(4 * ii + 3) * HP2PITCH]);
                    acc0 = fmaf(pv.x, p0.x, acc0); acc1 = fmaf(pv.x, p0.y, acc1);
                    acc0 = fmaf(pv.y, p1.x, acc0); acc1 = fmaf(pv.y, p1.y, acc1);
                    acc0 = fmaf(pv.z, p2.x, acc0); acc1 = fmaf(pv.z, p2.y, acc1);
                    acc0 = fmaf(pv.w, p3.x, acc0); acc1 = fmaf(pv.w, p3.y, acc1);
                }
            }
            float n2 = fmaf(acc0, acc0, acc1 * acc1);
            n2 += __shfl_xor_sync(FULL, n2, 1);
            n2 += __shfl_xor_sync(FULL, n2, 2);
            n2 += __shfl_xor_sync(FULL, n2, 4);
            float f = n2 / (1.f + n2) * rsqrtf(n2 + 1e-8f);
            out0 = acc0 * f;
            out1 = acc1 * f;
            if (it < 2)
                ((float2*)s_out)[s_ws * 80 + od2_ws] = make_float2(out0, out1);
        }

        if (it == 2) break;
        __syncthreads();               // s_out published

        // agreement: logits[s][i][o] (+)= sum_d priors*out, priors as 2x uint4
        for (int t = tid; t < NS * 360; t += NTHR) {
            int s = t / 360;
            int r = t % 360;
            int oo = r / 36;
            int i = r % 36;
            const uint4* pr4 = (const uint4*)(ph + (s * 36 + i) * HP2PITCH + oo * 8);
            uint4 A = pr4[0], B = pr4[1];
            const float4* ov4 = (const float4*)&s_out[s * 160 + oo * 16];
            float4 q0 = ov4[0], q1 = ov4[1], q2 = ov4[2], q3 = ov4[3];
            float sum = 0.f;
            float2 p;
            p = __half22float2(*(__half2*)&A.x); sum = fmaf(p.x, q0.x, sum); sum = fmaf(p.y, q0.y, sum);
            p = __half22float2(*(__half2*)&A.y); sum = fmaf(p.x, q0.z, sum); sum = fmaf(p.y, q0.w, sum);
            p = __half22float2(*(__half2*)&A.z); sum = fmaf(p.x, q1.x, sum); sum = fmaf(p.y, q1.y, sum);
            p = __half22float2(*(__half2*)&A.w); sum = fmaf(p.x, q1.z, sum); sum = fmaf(p.y, q1.w, sum);
            p = __half22float2(*(__half2*)&B.x); sum = fmaf(p.x, q2.x, sum); sum = fmaf(p.y, q2.y, sum);
            p = __half22float2(*(__half2*)&B.y); sum = fmaf(p.x, q2.z, sum); sum = fmaf(p.y, q2.w, sum);
            p = __half22float2(*(__half2*)&B.z); sum = fmaf(p.x, q3.x, sum); sum = fmaf(p.y, q3.y, sum);
            p = __half22float2(*(__half2*)&B.w); sum = fmaf(p.x, q3.z, sum); sum = fmaf(p.y, q3.w, sum);
            float* lp = &s_logit[(s * 36 + i) * LPITCH + oo];
            if (it == 0) *lp = sum;    // initial logits are zero
            else         *lp += sum;
        }
        // loop-top syncthreads orders agreement -> softmax
    }

    // ---- write output (float2, coalesced) ----
    if (tid < NS * 80)
        ((float2*)out_g)[(sample0 + s_ws) * 80 + od2_ws] = make_float2(out0, out1);
}

extern "C" void kernel_launch(void* const* d_in, const int* in_sizes, int n_in,
                              void* d_out, int out_size) {
    const float* x      = (const float*)d_in[0];
    const float* conv_w = (const float*)d_in[1];
    const float* lin_w  = (const float*)d_in[2];
    float* out = (float*)d_out;

    transpose_w_kernel<<<(46080 + 255) / 256, 256>>>(lin_w);

    size_t smem_f = (size_t)NS * 36 * HP2PITCH + NS * 36 * 8
                  + (size_t)NS * 360 + NS * 160
                  + (size_t)NS * 36 * LPITCH + NS * 9 + 288;
    size_t smem_bytes = smem_f * sizeof(float);   // 136,736 B
    cudaFuncSetAttribute(capsnet_kernel,
                         cudaFuncAttributeMaxDynamicSharedMemorySize,
                         (int)smem_bytes);

    int blocks = 16384 / NS;   // 2048
    capsnet_kernel<<<blocks, NTHR, smem_bytes>>>(x, conv_w, out);
}

// round 7
// speedup vs baseline: 1.7770x; 1.0847x over previous
#include <cuda_runtime.h>
#include <cuda_fp16.h>

// ---------------------------------------------------------------------------
// CapsNet forward, fully fused, fp16-priors, 3-CTA/SM edition.
//   conv(3x3,pad1) -> squash(8) -> priors einsum -> 3-iter dynamic routing
// Inputs: x[16384,1,3,3] f32, conv_w[32,1,3,3] f32, lin_w[10,36,16,8] f32.
// Output: [16384,10,16] f32.
//
// vs R6: NS 8->4, block 1024->512, __launch_bounds__(512,3) -> 3 resident
// CTAs/SM (48 warps, occ ~72%). Three independent barrier domains overlap
// narrow phases (softmax/ws) of one CTA with heavy phases (priors) of
// another, recovering the ~36% idle issue slots seen in R6.
// smem = 68,944 B/CTA (3x = 207 KB <= 228 KB).
// ---------------------------------------------------------------------------

#define NS 4
#define HP2PITCH 84         // half2 units per prior row (80 data + 4 pad)
#define LPITCH 11           // logits pitch (gcd(11,32)=1)
#define NTHR 512

__device__ float g_wt[36 * 8 * 160];   // Wt[i][l][od]

__global__ void transpose_w_kernel(const float* __restrict__ lin_w) {
    int t = blockIdx.x * 256 + threadIdx.x;
    if (t >= 46080) return;
    int od = t % 160;
    int il = t / 160;
    int l = il % 8;
    int i = il / 8;
    int o = od / 16;
    int d = od % 16;
    g_wt[t] = lin_w[((o * 36 + i) * 16 + d) * 8 + l];   // lin_w[o][i][d][l]
}

__global__ __launch_bounds__(NTHR, 3)
void capsnet_kernel(const float* __restrict__ x,
                    const float* __restrict__ conv_w,
                    float* __restrict__ out_g) {
    extern __shared__ float sm[];
    __half2* ph     = (__half2*)sm;                     // 4*36*84 h2 = 12096 slots
    float* s_caps   = sm + NS * 36 * HP2PITCH;          // 4*36*8 = 1152 f
    float* s_probst = s_caps + NS * 36 * 8;             // 4*10*36 = 1440 f
    float* s_out    = s_probst + NS * 360;              // 4*160 = 640 f
    float* s_logit  = s_out + NS * 160;                 // 4*36*11 = 1584 f
    float* s_x      = s_logit + NS * 36 * LPITCH;       // 36 f
    float* s_cw     = s_x + NS * 9;                     // 288 f
    // total = 17236 floats = 68,944 B

    const int tid = threadIdx.x;
    const int sample0 = blockIdx.x * NS;

    // ---- load inputs ----
    if (tid < NS * 9)  s_x[tid]  = x[sample0 * 9 + tid];
    else if (tid >= 64 && tid < 64 + 288) s_cw[tid - 64] = conv_w[tid - 64];
    __syncthreads();

    // ---- conv 3x3 pad1 on 3x3 input, into capsule layout ----
    for (int idx = tid; idx < NS * 288; idx += NTHR) {
        int s = idx / 288, r = idx % 288;
        int c = r / 9, p = r % 9;
        int h = p / 3, w = p % 3;
        float acc = 0.f;
        #pragma unroll
        for (int kh = 0; kh < 3; kh++) {
            int ih = h + kh - 1;
            if (ih < 0 || ih > 2) continue;
            #pragma unroll
            for (int kw = 0; kw < 3; kw++) {
                int iw = w + kw - 1;
                if (iw < 0 || iw > 2) continue;
                acc = fmaf(s_x[s * 9 + ih * 3 + iw], s_cw[c * 9 + kh * 3 + kw], acc);
            }
        }
        int g = c >> 3, l = c & 7;
        int i = p * 4 + g;
        s_caps[(s * 36 + i) * 8 + l] = acc;
    }
    __syncthreads();

    // ---- squash capsules over length 8 ----
    if (tid < NS * 36) {
        float* cp = &s_caps[tid * 8];
        float n2 = 0.f;
        #pragma unroll
        for (int l = 0; l < 8; l++) n2 = fmaf(cp[l], cp[l], n2);
        float f = n2 / (1.f + n2) * rsqrtf(n2 + 1e-8f);
        #pragma unroll
        for (int l = 0; l < 8; l++) cp[l] *= f;
    }
    __syncthreads();

    // ---- priors (half2 pairs): task = (i, od2); fp32 math, fp16 store ----
    for (int t = tid; t < 36 * 80; t += NTHR) {
        const int od2 = t % 80;
        const int i   = t / 80;
        const float2* wb = (const float2*)g_wt;
        float2 w0 = wb[(i * 8 + 0) * 80 + od2];
        float2 w1 = wb[(i * 8 + 1) * 80 + od2];
        float2 w2 = wb[(i * 8 + 2) * 80 + od2];
        float2 w3 = wb[(i * 8 + 3) * 80 + od2];
        float2 w4 = wb[(i * 8 + 4) * 80 + od2];
        float2 w5 = wb[(i * 8 + 5) * 80 + od2];
        float2 w6 = wb[(i * 8 + 6) * 80 + od2];
        float2 w7 = wb[(i * 8 + 7) * 80 + od2];
        #pragma unroll
        for (int s = 0; s < NS; s++) {
            const float4* cp = (const float4*)&s_caps[(s * 36 + i) * 8];
            float4 a = cp[0], b = cp[1];
            float a0 = w0.x * a.x, a1 = w0.y * a.x;
            a0 = fmaf(w1.x, a.y, a0); a1 = fmaf(w1.y, a.y, a1);
            a0 = fmaf(w2.x, a.z, a0); a1 = fmaf(w2.y, a.z, a1);
            a0 = fmaf(w3.x, a.w, a0); a1 = fmaf(w3.y, a.w, a1);
            a0 = fmaf(w4.x, b.x, a0); a1 = fmaf(w4.y, b.x, a1);
            a0 = fmaf(w5.x, b.y, a0); a1 = fmaf(w5.y, b.y, a1);
            a0 = fmaf(w6.x, b.z, a0); a1 = fmaf(w6.y, b.z, a1);
            a0 = fmaf(w7.x, b.w, a0); a1 = fmaf(w7.y, b.w, a1);
            ph[(s * 36 + i) * HP2PITCH + od2] = __floats2half2_rn(a0, a1);
        }
    }
    __syncthreads();

    // ---- dynamic routing (3 iterations) ----
    const unsigned FULL = 0xffffffffu;
    float out0 = 0.f, out1 = 0.f;
    const int s_ws   = tid / 80;       // ws task: (s, od2), tid < 320
    const int od2_ws = tid % 80;
    const int o_ws   = od2_ws / 8;

    for (int it = 0; it < 3; it++) {
        if (it > 0) {
            __syncthreads();           // agreement wrote s_logit
            if (tid < NS * 36) {       // softmax over o -> probs_t[s][o][i]
                const int s = tid / 36, i = tid % 36;
                const float* lg = &s_logit[tid * LPITCH];
                float m = lg[0];
                #pragma unroll
                for (int oo = 1; oo < 10; oo++) m = fmaxf(m, lg[oo]);
                float e[10];
                float sum = 0.f;
                #pragma unroll
                for (int oo = 0; oo < 10; oo++) { e[oo] = __expf(lg[oo] - m); sum += e[oo]; }
                float inv = 1.f / sum;
                #pragma unroll
                for (int oo = 0; oo < 10; oo++)
                    s_probst[(s * 10 + oo) * 36 + i] = e[oo] * inv;
            }
            __syncthreads();
        }

        // weighted sum over i + squash over d. 320 tasks (10 whole warps);
        // 8-lane shfl groups each hold one (s,o) with 2 d per lane.
        if (tid < NS * 80) {
            const __half2* pr = ph + s_ws * 36 * HP2PITCH + od2_ws;
            float acc0 = 0.f, acc1 = 0.f;
            if (it == 0) {
                #pragma unroll 4
                for (int i = 0; i < 36; i++) {
                    float2 p = __half22float2(pr[i * HP2PITCH]);
                    acc0 += p.x; acc1 += p.y;
                }
                acc0 *= 0.1f; acc1 *= 0.1f;    // softmax(0) over 10 classes
            } else {
                const float4* pb4 = (const float4*)&s_probst[(s_ws * 10 + o_ws) * 36];
                #pragma unroll
                for (int ii = 0; ii < 9; ii++) {
                    float4 pv = pb4[ii];
                    float2 p0 = __half22float2(pr[(4 * ii + 0) * HP2PITCH]);
                    float2 p1 = __half22float2(pr[(4 * ii + 1) * HP2PITCH]);
                    float2 p2 = __half22float2(pr[(4 * ii + 2) * HP2PITCH]);
                    float2 p3 = __half22float2(pr[(4 * ii + 3) * HP2PITCH]);
                    acc0 = fmaf(pv.x, p0.x, acc0); acc1 = fmaf(pv.x, p0.y, acc1);
                    acc0 = fmaf(pv.y, p1.x, acc0); acc1 = fmaf(pv.y, p1.y, acc1);
                    acc0 = fmaf(pv.z, p2.x, acc0); acc1 = fmaf(pv.z, p2.y, acc1);
                    acc0 = fmaf(pv.w, p3.x, acc0); acc1 = fmaf(pv.w, p3.y, acc1);
                }
            }
            float n2 = fmaf(acc0, acc0, acc1 * acc1);
            n2 += __shfl_xor_sync(FULL, n2, 1);
            n2 += __shfl_xor_sync(FULL, n2, 2);
            n2 += __shfl_xor_sync(FULL, n2, 4);
            float f = n2 / (1.f + n2) * rsqrtf(n2 + 1e-8f);
            out0 = acc0 * f;
            out1 = acc1 * f;
            if (it < 2)
                ((float2*)s_out)[s_ws * 80 + od2_ws] = make_float2(out0, out1);
        }

        if (it == 2) break;
        __syncthreads();               // s_out published

        // agreement: logits[s][i][o] (+)= sum_d priors*out, priors as 2x uint4
        for (int t = tid; t < NS * 360; t += NTHR) {
            int s = t / 360;
            int r = t % 360;
            int oo = r / 36;
            int i = r % 36;
            const uint4* pr4 = (const uint4*)(ph + (s * 36 + i) * HP2PITCH + oo * 8);
            uint4 A = pr4[0], B = pr4[1];
            const float4* ov4 = (const float4*)&s_out[s * 160 + oo * 16];
            float4 q0 = ov4[0], q1 = ov4[1], q2 = ov4[2], q3 = ov4[3];
            float sum = 0.f;
            float2 p;
            p = __half22float2(*(__half2*)&A.x); sum = fmaf(p.x, q0.x, sum); sum = fmaf(p.y, q0.y, sum);
            p = __half22float2(*(__half2*)&A.y); sum = fmaf(p.x, q0.z, sum); sum = fmaf(p.y, q0.w, sum);
            p = __half22float2(*(__half2*)&A.z); sum = fmaf(p.x, q1.x, sum); sum = fmaf(p.y, q1.y, sum);
            p = __half22float2(*(__half2*)&A.w); sum = fmaf(p.x, q1.z, sum); sum = fmaf(p.y, q1.w, sum);
            p = __half22float2(*(__half2*)&B.x); sum = fmaf(p.x, q2.x, sum); sum = fmaf(p.y, q2.y, sum);
            p = __half22float2(*(__half2*)&B.y); sum = fmaf(p.x, q2.z, sum); sum = fmaf(p.y, q2.w, sum);
            p = __half22float2(*(__half2*)&B.z); sum = fmaf(p.x, q3.x, sum); sum = fmaf(p.y, q3.y, sum);
            p = __half22float2(*(__half2*)&B.w); sum = fmaf(p.x, q3.z, sum); sum = fmaf(p.y, q3.w, sum);
            float* lp = &s_logit[(s * 36 + i) * LPITCH + oo];
            if (it == 0) *lp = sum;    // initial logits are zero
            else         *lp += sum;
        }
        // loop-top syncthreads orders agreement -> softmax
    }

    // ---- write output (float2, coalesced) ----
    if (tid < NS * 80)
        ((float2*)out_g)[(sample0 + s_ws) * 80 + od2_ws] = make_float2(out0, out1);
}

extern "C" void kernel_launch(void* const* d_in, const int* in_sizes, int n_in,
                              void* d_out, int out_size) {
    const float* x      = (const float*)d_in[0];
    const float* conv_w = (const float*)d_in[1];
    const float* lin_w  = (const float*)d_in[2];
    float* out = (float*)d_out;

    transpose_w_kernel<<<(46080 + 255) / 256, 256>>>(lin_w);

    size_t smem_f = (size_t)NS * 36 * HP2PITCH + NS * 36 * 8
                  + (size_t)NS * 360 + NS * 160
                  + (size_t)NS * 36 * LPITCH + NS * 9 + 288;
    size_t smem_bytes = smem_f * sizeof(float);   // 68,944 B -> 3 CTAs/SM
    cudaFuncSetAttribute(capsnet_kernel,
                         cudaFuncAttributeMaxDynamicSharedMemorySize,
                         (int)smem_bytes);

    int blocks = 16384 / NS;   // 4096
    capsnet_kernel<<<blocks, NTHR, smem_bytes>>>(x, conv_w, out);
}

// round 8
// speedup vs baseline: 1.8059x; 1.0163x over previous
#include <cuda_runtime.h>
#include <cuda_fp16.h>

// ---------------------------------------------------------------------------
// CapsNet forward, fully fused, fp16-priors + fp16-weights, 3-CTA/SM.
//   conv(3x3,pad1) -> squash(8) -> priors einsum -> 3-iter dynamic routing
// Inputs: x[16384,1,3,3] f32, conv_w[32,1,3,3] f32, lin_w[10,36,16,8] f32.
// Output: [16384,10,16] f32.
//
// vs R7: routing weights stored fp16 in layout [i][od2][odp][l] so each
// priors task loads its 16 weights as 2x LDG.128 (was 8x LDG.64 fp32):
// halves the dominant weight-LDG wavefronts (1440->720/block) and L2 bytes.
// All arithmetic fp32 (weights converted once per task, reused x4 samples).
// ---------------------------------------------------------------------------

#define NS 4
#define HP2PITCH 84         // half2 units per prior row (80 data + 4 pad)
#define LPITCH 11           // logits pitch (gcd(11,32)=1)
#define NTHR 512

__device__ __half g_wt_h[36 * 80 * 16];   // [i][od2][odp][l]

__global__ void transpose_w_kernel(const float* __restrict__ lin_w) {
    int t = blockIdx.x * 256 + threadIdx.x;
    if (t >= 46080) return;
    int l   = t & 7;
    int odp = (t >> 3) & 1;
    int od2 = (t >> 4) % 80;
    int i   = t / 1280;
    int od  = od2 * 2 + odp;
    int o   = od / 16;
    int d   = od % 16;
    g_wt_h[t] = __float2half(lin_w[((o * 36 + i) * 16 + d) * 8 + l]);
}

__global__ __launch_bounds__(NTHR, 3)
void capsnet_kernel(const float* __restrict__ x,
                    const float* __restrict__ conv_w,
                    float* __restrict__ out_g) {
    extern __shared__ float sm[];
    __half2* ph     = (__half2*)sm;                     // 4*36*84 h2
    float* s_caps   = sm + NS * 36 * HP2PITCH;          // 1152 f
    float* s_probst = s_caps + NS * 36 * 8;             // 1440 f
    float* s_out    = s_probst + NS * 360;              // 640 f
    float* s_logit  = s_out + NS * 160;                 // 1584 f
    float* s_x      = s_logit + NS * 36 * LPITCH;       // 36 f
    float* s_cw     = s_x + NS * 9;                     // 288 f
    // total = 17236 floats = 68,944 B

    const int tid = threadIdx.x;
    const int sample0 = blockIdx.x * NS;

    // ---- load inputs ----
    if (tid < NS * 9)  s_x[tid]  = x[sample0 * 9 + tid];
    else if (tid >= 64 && tid < 64 + 288) s_cw[tid - 64] = conv_w[tid - 64];
    __syncthreads();

    // ---- conv 3x3 pad1 on 3x3 input, into capsule layout ----
    for (int idx = tid; idx < NS * 288; idx += NTHR) {
        int s = idx / 288, r = idx % 288;
        int c = r / 9, p = r % 9;
        int h = p / 3, w = p % 3;
        float acc = 0.f;
        #pragma unroll
        for (int kh = 0; kh < 3; kh++) {
            int ih = h + kh - 1;
            if (ih < 0 || ih > 2) continue;
            #pragma unroll
            for (int kw = 0; kw < 3; kw++) {
                int iw = w + kw - 1;
                if (iw < 0 || iw > 2) continue;
                acc = fmaf(s_x[s * 9 + ih * 3 + iw], s_cw[c * 9 + kh * 3 + kw], acc);
            }
        }
        int g = c >> 3, l = c & 7;
        int i = p * 4 + g;
        s_caps[(s * 36 + i) * 8 + l] = acc;
    }
    __syncthreads();

    // ---- squash capsules over length 8 ----
    if (tid < NS * 36) {
        float* cp = &s_caps[tid * 8];
        float n2 = 0.f;
        #pragma unroll
        for (int l = 0; l < 8; l++) n2 = fmaf(cp[l], cp[l], n2);
        float f = n2 / (1.f + n2) * rsqrtf(n2 + 1e-8f);
        #pragma unroll
        for (int l = 0; l < 8; l++) cp[l] *= f;
    }
    __syncthreads();

    // ---- priors (half2 pairs): task = (i, od2); fp16 weights, fp32 math ----
    for (int t = tid; t < 36 * 80; t += NTHR) {
        const int od2 = t % 80;
        const int i   = t / 80;
        const uint4* wp = (const uint4*)(g_wt_h + (size_t)(i * 80 + od2) * 16);
        uint4 W0 = wp[0];              // 8 halfs: weights for od even, l=0..7
        uint4 W1 = wp[1];              // 8 halfs: weights for od odd,  l=0..7
        float w0[8], w1[8];
        {
            const __half2* h0 = (const __half2*)&W0;
            const __half2* h1 = (const __half2*)&W1;
            #pragma unroll
            for (int k = 0; k < 4; k++) {
                float2 f0 = __half22float2(h0[k]);
                float2 f1 = __half22float2(h1[k]);
                w0[2 * k] = f0.x; w0[2 * k + 1] = f0.y;
                w1[2 * k] = f1.x; w1[2 * k + 1] = f1.y;
            }
        }
        #pragma unroll
        for (int s = 0; s < NS; s++) {
            const float4* cp = (const float4*)&s_caps[(s * 36 + i) * 8];
            float4 a = cp[0], b = cp[1];
            float c0 = a.x, c1 = a.y, c2 = a.z, c3 = a.w;
            float c4 = b.x, c5 = b.y, c6 = b.z, c7 = b.w;
            float a0 = w0[0] * c0, a1 = w1[0] * c0;
            a0 = fmaf(w0[1], c1, a0); a1 = fmaf(w1[1], c1, a1);
            a0 = fmaf(w0[2], c2, a0); a1 = fmaf(w1[2], c2, a1);
            a0 = fmaf(w0[3], c3, a0); a1 = fmaf(w1[3], c3, a1);
            a0 = fmaf(w0[4], c4, a0); a1 = fmaf(w1[4], c4, a1);
            a0 = fmaf(w0[5], c5, a0); a1 = fmaf(w1[5], c5, a1);
            a0 = fmaf(w0[6], c6, a0); a1 = fmaf(w1[6], c6, a1);
            a0 = fmaf(w0[7], c7, a0); a1 = fmaf(w1[7], c7, a1);
            ph[(s * 36 + i) * HP2PITCH + od2] = __floats2half2_rn(a0, a1);
        }
    }
    __syncthreads();

    // ---- dynamic routing (3 iterations) ----
    const unsigned FULL = 0xffffffffu;
    float out0 = 0.f, out1 = 0.f;
    const int s_ws   = tid / 80;       // ws task: (s, od2), tid < 320
    const int od2_ws = tid % 80;
    const int o_ws   = od2_ws / 8;

    for (int it = 0; it < 3; it++) {
        if (it > 0) {
            __syncthreads();           // agreement wrote s_logit
            if (tid < NS * 36) {       // softmax over o -> probs_t[s][o][i]
                const int s = tid / 36, i = tid % 36;
                const float* lg = &s_logit[tid * LPITCH];
                float m = lg[0];
                #pragma unroll
                for (int oo = 1; oo < 10; oo++) m = fmaxf(m, lg[oo]);
                float e[10];
                float sum = 0.f;
                #pragma unroll
                for (int oo = 0; oo < 10; oo++) { e[oo] = __expf(lg[oo] - m); sum += e[oo]; }
                float inv = 1.f / sum;
                #pragma unroll
                for (int oo = 0; oo < 10; oo++)
                    s_probst[(s * 10 + oo) * 36 + i] = e[oo] * inv;
            }
            __syncthreads();
        }

        // weighted sum over i + squash over d. 320 tasks (10 whole warps);
        // 8-lane shfl groups each hold one (s,o) with 2 d per lane.
        if (tid < NS * 80) {
            const __half2* pr = ph + s_ws * 36 * HP2PITCH + od2_ws;
            float acc0 = 0.f, acc1 = 0.f;
            if (it == 0) {
                #pragma unroll 4
                for (int i = 0; i < 36; i++) {
                    float2 p = __half22float2(pr[i * HP2PITCH]);
                    acc0 += p.x; acc1 += p.y;
                }
                acc0 *= 0.1f; acc1 *= 0.1f;    // softmax(0) over 10 classes
            } else {
                const float4* pb4 = (const float4*)&s_probst[(s_ws * 10 + o_ws) * 36];
                #pragma unroll
                for (int ii = 0; ii < 9; ii++) {
                    float4 pv = pb4[ii];
                    float2 p0 = __half22float2(pr[(4 * ii + 0) * HP2PITCH]);
                    float2 p1 = __half22float2(pr[(4 * ii + 1) * HP2PITCH]);
                    float2 p2 = __half22float2(pr[(4 * ii + 2) * HP2PITCH]);
                    float2 p3 = __half22float2(pr[(4 * ii + 3) * HP2PITCH]);
                    acc0 = fmaf(pv.x, p0.x, acc0); acc1 = fmaf(pv.x, p0.y, acc1);
                    acc0 = fmaf(pv.y, p1.x, acc0); acc1 = fmaf(pv.y, p1.y, acc1);
                    acc0 = fmaf(pv.z, p2.x, acc0); acc1 = fmaf(pv.z, p2.y, acc1);
                    acc0 = fmaf(pv.w, p3.x, acc0); acc1 = fmaf(pv.w, p3.y, acc1);
                }
            }
            float n2 = fmaf(acc0, acc0, acc1 * acc1);
            n2 += __shfl_xor_sync(FULL, n2, 1);
            n2 += __shfl_xor_sync(FULL, n2, 2);
            n2 += __shfl_xor_sync(FULL, n2, 4);
            float f = n2 / (1.f + n2) * rsqrtf(n2 + 1e-8f);
            out0 = acc0 * f;
            out1 = acc1 * f;
            if (it < 2)
                ((float2*)s_out)[s_ws * 80 + od2_ws] = make_float2(out0, out1);
        }

        if (it == 2) break;
        __syncthreads();               // s_out published

        // agreement: logits[s][i][o] (+)= sum_d priors*out, priors as 2x uint4
        for (int t = tid; t < NS * 360; t += NTHR) {
            int s = t / 360;
            int r = t % 360;
            int oo = r / 36;
            int i = r % 36;
            const uint4* pr4 = (const uint4*)(ph + (s * 36 + i) * HP2PITCH + oo * 8);
            uint4 A = pr4[0], B = pr4[1];
            const float4* ov4 = (const float4*)&s_out[s * 160 + oo * 16];
            float4 q0 = ov4[0], q1 = ov4[1], q2 = ov4[2], q3 = ov4[3];
            float sum = 0.f;
            float2 p;
            p = __half22float2(*(__half2*)&A.x); sum = fmaf(p.x, q0.x, sum); sum = fmaf(p.y, q0.y, sum);
            p = __half22float2(*(__half2*)&A.y); sum = fmaf(p.x, q0.z, sum); sum = fmaf(p.y, q0.w, sum);
            p = __half22float2(*(__half2*)&A.z); sum = fmaf(p.x, q1.x, sum); sum = fmaf(p.y, q1.y, sum);
            p = __half22float2(*(__half2*)&A.w); sum = fmaf(p.x, q1.z, sum); sum = fmaf(p.y, q1.w, sum);
            p = __half22float2(*(__half2*)&B.x); sum = fmaf(p.x, q2.x, sum); sum = fmaf(p.y, q2.y, sum);
            p = __half22float2(*(__half2*)&B.y); sum = fmaf(p.x, q2.z, sum); sum = fmaf(p.y, q2.w, sum);
            p = __half22float2(*(__half2*)&B.z); sum = fmaf(p.x, q3.x, sum); sum = fmaf(p.y, q3.y, sum);
            p = __half22float2(*(__half2*)&B.w); sum = fmaf(p.x, q3.z, sum); sum = fmaf(p.y, q3.w, sum);
            float* lp = &s_logit[(s * 36 + i) * LPITCH + oo];
            if (it == 0) *lp = sum;    // initial logits are zero
            else         *lp += sum;
        }
        // loop-top syncthreads orders agreement -> softmax
    }

    // ---- write output (float2, coalesced) ----
    if (tid < NS * 80)
        ((float2*)out_g)[(sample0 + s_ws) * 80 + od2_ws] = make_float2(out0, out1);
}

extern "C" void kernel_launch(void* const* d_in, const int* in_sizes, int n_in,
                              void* d_out, int out_size) {
    const float* x      = (const float*)d_in[0];
    const float* conv_w = (const float*)d_in[1];
    const float* lin_w  = (const float*)d_in[2];
    float* out = (float*)d_out;

    transpose_w_kernel<<<(46080 + 255) / 256, 256>>>(lin_w);

    size_t smem_f = (size_t)NS * 36 * HP2PITCH + NS * 36 * 8
                  + (size_t)NS * 360 + NS * 160
                  + (size_t)NS * 36 * LPITCH + NS * 9 + 288;
    size_t smem_bytes = smem_f * sizeof(float);   // 68,944 B -> 3 CTAs/SM
    cudaFuncSetAttribute(capsnet_kernel,
                         cudaFuncAttributeMaxDynamicSharedMemorySize,
                         (int)smem_bytes);

    int blocks = 16384 / NS;   // 4096
    capsnet_kernel<<<blocks, NTHR, smem_bytes>>>(x, conv_w, out);
}

// round 10
// speedup vs baseline: 1.8276x; 1.0120x over previous
#include <cuda_runtime.h>
#include <cuda_fp16.h>

// ---------------------------------------------------------------------------
// CapsNet forward, fully fused, fp16-priors + fp16-weights, 3-CTA/SM.
//   conv(3x3,pad1) -> squash(8) -> priors einsum -> 3-iter dynamic routing
// Inputs: x[16384,1,3,3] f32, conv_w[32,1,3,3] f32, lin_w[10,36,16,8] f32.
// Output: [16384,10,16] f32.
//
// vs R8: block 512 -> 640 threads with __launch_bounds__(640,3):
// 3 CTAs x 20 warps = 60 warps/SM (94% occupancy vs 70%) at identical
// smem/NS/numerics. 640 % 80 == 0 makes od2 loop-invariant in the priors
// phase (no per-round div/mod). Reg cap 34 (was 38 used) - minor squeeze.
// (Resubmission of R9 - GPU acquisition timed out before it ever ran.)
// ---------------------------------------------------------------------------

#define NS 4
#define HP2PITCH 84         // half2 units per prior row (80 data + 4 pad)
#define LPITCH 11           // logits pitch (gcd(11,32)=1)
#define NTHR 640

__device__ __half g_wt_h[36 * 80 * 16];   // [i][od2][odp][l]

__global__ void transpose_w_kernel(const float* __restrict__ lin_w) {
    int t = blockIdx.x * 256 + threadIdx.x;
    if (t >= 46080) return;
    int l   = t & 7;
    int odp = (t >> 3) & 1;
    int od2 = (t >> 4) % 80;
    int i   = t / 1280;
    int od  = od2 * 2 + odp;
    int o   = od / 16;
    int d   = od % 16;
    g_wt_h[t] = __float2half(lin_w[((o * 36 + i) * 16 + d) * 8 + l]);
}

__global__ __launch_bounds__(NTHR, 3)
void capsnet_kernel(const float* __restrict__ x,
                    const float* __restrict__ conv_w,
                    float* __restrict__ out_g) {
    extern __shared__ float sm[];
    __half2* ph     = (__half2*)sm;                     // 4*36*84 h2
    float* s_caps   = sm + NS * 36 * HP2PITCH;          // 1152 f
    float* s_probst = s_caps + NS * 36 * 8;             // 1440 f
    float* s_out    = s_probst + NS * 360;              // 640 f
    float* s_logit  = s_out + NS * 160;                 // 1584 f
    float* s_x      = s_logit + NS * 36 * LPITCH;       // 36 f
    float* s_cw     = s_x + NS * 9;                     // 288 f
    // total = 17236 floats = 68,944 B

    const int tid = threadIdx.x;
    const int sample0 = blockIdx.x * NS;

    // ---- load inputs ----
    if (tid < NS * 9)  s_x[tid]  = x[sample0 * 9 + tid];
    else if (tid >= 64 && tid < 64 + 288) s_cw[tid - 64] = conv_w[tid - 64];
    __syncthreads();

    // ---- conv 3x3 pad1 on 3x3 input, into capsule layout ----
    for (int idx = tid; idx < NS * 288; idx += NTHR) {
        int s = idx / 288, r = idx % 288;
        int c = r / 9, p = r % 9;
        int h = p / 3, w = p % 3;
        float acc = 0.f;
        #pragma unroll
        for (int kh = 0; kh < 3; kh++) {
            int ih = h + kh - 1;
            if (ih < 0 || ih > 2) continue;
            #pragma unroll
            for (int kw = 0; kw < 3; kw++) {
                int iw = w + kw - 1;
                if (iw < 0 || iw > 2) continue;
                acc = fmaf(s_x[s * 9 + ih * 3 + iw], s_cw[c * 9 + kh * 3 + kw], acc);
            }
        }
        int g = c >> 3, l = c & 7;
        int i = p * 4 + g;
        s_caps[(s * 36 + i) * 8 + l] = acc;
    }
    __syncthreads();

    // ---- squash capsules over length 8 ----
    if (tid < NS * 36) {
        float* cp = &s_caps[tid * 8];
        float n2 = 0.f;
        #pragma unroll
        for (int l = 0; l < 8; l++) n2 = fmaf(cp[l], cp[l], n2);
        float f = n2 / (1.f + n2) * rsqrtf(n2 + 1e-8f);
        #pragma unroll
        for (int l = 0; l < 8; l++) cp[l] *= f;
    }
    __syncthreads();

    // ---- priors (half2 pairs): thread owns fixed od2; i strides by 8 ----
    {
        const int od2 = tid % 80;
        for (int i = tid / 80; i < 36; i += 8) {
            const uint4* wp = (const uint4*)(g_wt_h + (size_t)(i * 80 + od2) * 16);
            uint4 W0 = wp[0];          // 8 halfs: weights for od even, l=0..7
            uint4 W1 = wp[1];          // 8 halfs: weights for od odd,  l=0..7
            float w0[8], w1[8];
            {
                const __half2* h0 = (const __half2*)&W0;
                const __half2* h1 = (const __half2*)&W1;
                #pragma unroll
                for (int k = 0; k < 4; k++) {
                    float2 f0 = __half22float2(h0[k]);
                    float2 f1 = __half22float2(h1[k]);
                    w0[2 * k] = f0.x; w0[2 * k + 1] = f0.y;
                    w1[2 * k] = f1.x; w1[2 * k + 1] = f1.y;
                }
            }
            #pragma unroll
            for (int s = 0; s < NS; s++) {
                const float4* cp = (const float4*)&s_caps[(s * 36 + i) * 8];
                float4 a = cp[0], b = cp[1];
                float a0 = w0[0] * a.x, a1 = w1[0] * a.x;
                a0 = fmaf(w0[1], a.y, a0); a1 = fmaf(w1[1], a.y, a1);
                a0 = fmaf(w0[2], a.z, a0); a1 = fmaf(w1[2], a.z, a1);
                a0 = fmaf(w0[3], a.w, a0); a1 = fmaf(w1[3], a.w, a1);
                a0 = fmaf(w0[4], b.x, a0); a1 = fmaf(w1[4], b.x, a1);
                a0 = fmaf(w0[5], b.y, a0); a1 = fmaf(w1[5], b.y, a1);
                a0 = fmaf(w0[6], b.z, a0); a1 = fmaf(w1[6], b.z, a1);
                a0 = fmaf(w0[7], b.w, a0); a1 = fmaf(w1[7], b.w, a1);
                ph[(s * 36 + i) * HP2PITCH + od2] = __floats2half2_rn(a0, a1);
            }
        }
    }
    __syncthreads();

    // ---- dynamic routing (3 iterations) ----
    const unsigned FULL = 0xffffffffu;
    float out0 = 0.f, out1 = 0.f;
    const int s_ws   = tid / 80;       // ws task: (s, od2), tid < 320
    const int od2_ws = tid % 80;
    const int o_ws   = od2_ws / 8;

    for (int it = 0; it < 3; it++) {
        if (it > 0) {
            __syncthreads();           // agreement wrote s_logit
            if (tid < NS * 36) {       // softmax over o -> probs_t[s][o][i]
                const int s = tid / 36, i = tid % 36;
                const float* lg = &s_logit[tid * LPITCH];
                float m = lg[0];
                #pragma unroll
                for (int oo = 1; oo < 10; oo++) m = fmaxf(m, lg[oo]);
                float e[10];
                float sum = 0.f;
                #pragma unroll
                for (int oo = 0; oo < 10; oo++) { e[oo] = __expf(lg[oo] - m); sum += e[oo]; }
                float inv = 1.f / sum;
                #pragma unroll
                for (int oo = 0; oo < 10; oo++)
                    s_probst[(s * 10 + oo) * 36 + i] = e[oo] * inv;
            }
            __syncthreads();
        }

        // weighted sum over i + squash over d. 320 tasks (10 whole warps);
        // 8-lane shfl groups each hold one (s,o) with 2 d per lane.
        if (tid < NS * 80) {
            const __half2* pr = ph + s_ws * 36 * HP2PITCH + od2_ws;
            float acc0 = 0.f, acc1 = 0.f;
            if (it == 0) {
                #pragma unroll 4
                for (int i = 0; i < 36; i++) {
                    float2 p = __half22float2(pr[i * HP2PITCH]);
                    acc0 += p.x; acc1 += p.y;
                }
                acc0 *= 0.1f; acc1 *= 0.1f;    // softmax(0) over 10 classes
            } else {
                const float4* pb4 = (const float4*)&s_probst[(s_ws * 10 + o_ws) * 36];
                #pragma unroll
                for (int ii = 0; ii < 9; ii++) {
                    float4 pv = pb4[ii];
                    float2 p0 = __half22float2(pr[(4 * ii + 0) * HP2PITCH]);
                    float2 p1 = __half22float2(pr[(4 * ii + 1) * HP2PITCH]);
                    float2 p2 = __half22float2(pr[(4 * ii + 2) * HP2PITCH]);
                    float2 p3 = __half22float2(pr[(4 * ii + 3) * HP2PITCH]);
                    acc0 = fmaf(pv.x, p0.x, acc0); acc1 = fmaf(pv.x, p0.y, acc1);
                    acc0 = fmaf(pv.y, p1.x, acc0); acc1 = fmaf(pv.y, p1.y, acc1);
                    acc0 = fmaf(pv.z, p2.x, acc0); acc1 = fmaf(pv.z, p2.y, acc1);
                    acc0 = fmaf(pv.w, p3.x, acc0); acc1 = fmaf(pv.w, p3.y, acc1);
                }
            }
            float n2 = fmaf(acc0, acc0, acc1 * acc1);
            n2 += __shfl_xor_sync(FULL, n2, 1);
            n2 += __shfl_xor_sync(FULL, n2, 2);
            n2 += __shfl_xor_sync(FULL, n2, 4);
            float f = n2 / (1.f + n2) * rsqrtf(n2 + 1e-8f);
            out0 = acc0 * f;
            out1 = acc1 * f;
            if (it < 2)
                ((float2*)s_out)[s_ws * 80 + od2_ws] = make_float2(out0, out1);
        }

        if (it == 2) break;
        __syncthreads();               // s_out published

        // agreement: logits[s][i][o] (+)= sum_d priors*out, priors as 2x uint4
        for (int t = tid; t < NS * 360; t += NTHR) {
            int s = t / 360;
            int r = t % 360;
            int oo = r / 36;
            int i = r % 36;
            const uint4* pr4 = (const uint4*)(ph + (s * 36 + i) * HP2PITCH + oo * 8);
            uint4 A = pr4[0], B = pr4[1];
            const float4* ov4 = (const float4*)&s_out[s * 160 + oo * 16];
            float4 q0 = ov4[0], q1 = ov4[1], q2 = ov4[2], q3 = ov4[3];
            float sum = 0.f;
            float2 p;
            p = __half22float2(*(__half2*)&A.x); sum = fmaf(p.x, q0.x, sum); sum = fmaf(p.y, q0.y, sum);
            p = __half22float2(*(__half2*)&A.y); sum = fmaf(p.x, q0.z, sum); sum = fmaf(p.y, q0.w, sum);
            p = __half22float2(*(__half2*)&A.z); sum = fmaf(p.x, q1.x, sum); sum = fmaf(p.y, q1.y, sum);
            p = __half22float2(*(__half2*)&A.w); sum = fmaf(p.x, q1.z, sum); sum = fmaf(p.y, q1.w, sum);
            p = __half22float2(*(__half2*)&B.x); sum = fmaf(p.x, q2.x, sum); sum = fmaf(p.y, q2.y, sum);
            p = __half22float2(*(__half2*)&B.y); sum = fmaf(p.x, q2.z, sum); sum = fmaf(p.y, q2.w, sum);
            p = __half22float2(*(__half2*)&B.z); sum = fmaf(p.x, q3.x, sum); sum = fmaf(p.y, q3.y, sum);
            p = __half22float2(*(__half2*)&B.w); sum = fmaf(p.x, q3.z, sum); sum = fmaf(p.y, q3.w, sum);
            float* lp = &s_logit[(s * 36 + i) * LPITCH + oo];
            if (it == 0) *lp = sum;    // initial logits are zero
            else         *lp += sum;
        }
        // loop-top syncthreads orders agreement -> softmax
    }

    // ---- write output (float2, coalesced) ----
    if (tid < NS * 80)
        ((float2*)out_g)[(sample0 + s_ws) * 80 + od2_ws] = make_float2(out0, out1);
}

extern "C" void kernel_launch(void* const* d_in, const int* in_sizes, int n_in,
                              void* d_out, int out_size) {
    const float* x      = (const float*)d_in[0];
    const float* conv_w = (const float*)d_in[1];
    const float* lin_w  = (const float*)d_in[2];
    float* out = (float*)d_out;

    transpose_w_kernel<<<(46080 + 255) / 256, 256>>>(lin_w);

    size_t smem_f = (size_t)NS * 36 * HP2PITCH + NS * 36 * 8
                  + (size_t)NS * 360 + NS * 160
                  + (size_t)NS * 36 * LPITCH + NS * 9 + 288;
    size_t smem_bytes = smem_f * sizeof(float);   // 68,944 B -> 3 CTAs/SM
    cudaFuncSetAttribute(capsnet_kernel,
                         cudaFuncAttributeMaxDynamicSharedMemorySize,
                         (int)smem_bytes);

    int blocks = 16384 / NS;   // 4096
    capsnet_kernel<<<blocks, NTHR, smem_bytes>>>(x, conv_w, out);
}

// round 13
// speedup vs baseline: 1.9146x; 1.0476x over previous
#include <cuda_runtime.h>
#include <cuda_fp16.h>

// ---------------------------------------------------------------------------
// CapsNet forward, fully fused. HFMA2-priors edition.
//   conv(3x3,pad1) -> squash(8) -> priors einsum -> 3-iter dynamic routing
// Inputs: x[16384,1,3,3] f32, conv_w[32,1,3,3] f32, lin_w[10,36,16,8] f32.
// Output: [16384,10,16] f32.
//
// vs R10: the priors einsum runs natively on HFMA2:
//  - caps stored as DUPLICATED half2 (c,c) in-place after squash (same 32B
//    per capsule row -> identical LDS wavefronts),
//  - weights half2 layout [i][od2][l][odp] so each half2 = (w_od_even, w_od_odd),
//  - per sample: 8 HFMA2 (two 4-term chains) + 1 HADD2 + 1 STS
//    (was 16 FFMA + 8 converts amortized + pack) -> priors instrs -44%,
//    block instrs ~-22%. fp16 accumulate in 2 chains bounds rounding noise.
// 640 threads, __launch_bounds__(640,3), smem 68,944 B -> 3 CTAs/SM.
// (Second resubmission - R11 and R12 both hit GPUAcquisitionTimeout; this
//  kernel has never run.)
// ---------------------------------------------------------------------------

#define NS 4
#define HP2PITCH 84         // half2 units per prior row (80 data + 4 pad)
#define LPITCH 11           // logits pitch (gcd(11,32)=1)
#define NTHR 640

__device__ __half g_wt_h[36 * 80 * 16];   // [i][od2][l][odp]: half2 = (w_e, w_o)

__global__ void transpose_w_kernel(const float* __restrict__ lin_w) {
    int t = blockIdx.x * 256 + threadIdx.x;
    if (t >= 46080) return;
    int odp = t & 1;
    int l   = (t >> 1) & 7;
    int od2 = (t >> 4) % 80;
    int i   = t / 1280;
    int od  = od2 * 2 + odp;
    int o   = od / 16;
    int d   = od % 16;
    g_wt_h[t] = __float2half(lin_w[((o * 36 + i) * 16 + d) * 8 + l]);
}

__global__ __launch_bounds__(NTHR, 3)
void capsnet_kernel(const float* __restrict__ x,
                    const float* __restrict__ conv_w,
                    float* __restrict__ out_g) {
    extern __shared__ float sm[];
    __half2* ph     = (__half2*)sm;                     // 4*36*84 h2
    float* s_caps   = sm + NS * 36 * HP2PITCH;          // 1152 f (fp32 conv out,
                                                        //  then dup-half2 after squash)
    float* s_probst = s_caps + NS * 36 * 8;             // 1440 f
    float* s_out    = s_probst + NS * 360;              // 640 f
    float* s_logit  = s_out + NS * 160;                 // 1584 f
    float* s_x      = s_logit + NS * 36 * LPITCH;       // 36 f
    float* s_cw     = s_x + NS * 9;                     // 288 f
    // total = 17236 floats = 68,944 B

    const int tid = threadIdx.x;
    const int sample0 = blockIdx.x * NS;

    // ---- load inputs ----
    if (tid < NS * 9)  s_x[tid]  = x[sample0 * 9 + tid];
    else if (tid >= 64 && tid < 64 + 288) s_cw[tid - 64] = conv_w[tid - 64];
    __syncthreads();

    // ---- conv 3x3 pad1 on 3x3 input, into capsule layout (fp32) ----
    for (int idx = tid; idx < NS * 288; idx += NTHR) {
        int s = idx / 288, r = idx % 288;
        int c = r / 9, p = r % 9;
        int h = p / 3, w = p % 3;
        float acc = 0.f;
        #pragma unroll
        for (int kh = 0; kh < 3; kh++) {
            int ih = h + kh - 1;
            if (ih < 0 || ih > 2) continue;
            #pragma unroll
            for (int kw = 0; kw < 3; kw++) {
                int iw = w + kw - 1;
                if (iw < 0 || iw > 2) continue;
                acc = fmaf(s_x[s * 9 + ih * 3 + iw], s_cw[c * 9 + kh * 3 + kw], acc);
            }
        }
        int g = c >> 3, l = c & 7;
        int i = p * 4 + g;
        s_caps[(s * 36 + i) * 8 + l] = acc;
    }
    __syncthreads();

    // ---- squash over length 8; write back IN-PLACE as duplicated half2 ----
    if (tid < NS * 36) {
        float* cp = &s_caps[tid * 8];
        float v[8];
        float n2 = 0.f;
        #pragma unroll
        for (int l = 0; l < 8; l++) { v[l] = cp[l]; n2 = fmaf(v[l], v[l], n2); }
        float f = n2 / (1.f + n2) * rsqrtf(n2 + 1e-8f);
        __half2* cph = (__half2*)cp;   // same 32B row, same thread: no hazard
        #pragma unroll
        for (int l = 0; l < 8; l++) cph[l] = __float2half2_rn(v[l] * f);
    }
    __syncthreads();

    // ---- priors via HFMA2: thread owns fixed od2; i strides by 8 ----
    // w[l] = (w_even, w_odd); c[l] = (c,c) dup  =>  hfma2 lane0->od_e, lane1->od_o
    {
        const int od2 = tid % 80;
        for (int i = tid / 80; i < 36; i += 8) {
            const uint4* wp = (const uint4*)(g_wt_h + (size_t)(i * 80 + od2) * 16);
            uint4 W0 = wp[0];          // l = 0..3 pairs
            uint4 W1 = wp[1];          // l = 4..7 pairs
            const __half2* w03 = (const __half2*)&W0;
            const __half2* w47 = (const __half2*)&W1;
            #pragma unroll
            for (int s = 0; s < NS; s++) {
                const uint4* cp = (const uint4*)&s_caps[(s * 36 + i) * 8];
                uint4 C0 = cp[0], C1 = cp[1];
                const __half2* c03 = (const __half2*)&C0;
                const __half2* c47 = (const __half2*)&C1;
                // two 4-term chains, merged once (bounds fp16 accum noise)
                __half2 a = __hmul2(w03[0], c03[0]);
                a = __hfma2(w03[1], c03[1], a);
                a = __hfma2(w03[2], c03[2], a);
                a = __hfma2(w03[3], c03[3], a);
                __half2 b = __hmul2(w47[0], c47[0]);
                b = __hfma2(w47[1], c47[1], b);
                b = __hfma2(w47[2], c47[2], b);
                b = __hfma2(w47[3], c47[3], b);
                ph[(s * 36 + i) * HP2PITCH + od2] = __hadd2(a, b);
            }
        }
    }
    __syncthreads();

    // ---- dynamic routing (3 iterations) ----
    const unsigned FULL = 0xffffffffu;
    float out0 = 0.f, out1 = 0.f;
    const int s_ws   = tid / 80;       // ws task: (s, od2), tid < 320
    const int od2_ws = tid % 80;
    const int o_ws   = od2_ws / 8;

    for (int it = 0; it < 3; it++) {
        if (it > 0) {
            __syncthreads();           // agreement wrote s_logit
            if (tid < NS * 36) {       // softmax over o -> probs_t[s][o][i]
                const int s = tid / 36, i = tid % 36;
                const float* lg = &s_logit[tid * LPITCH];
                float m = lg[0];
                #pragma unroll
                for (int oo = 1; oo < 10; oo++) m = fmaxf(m, lg[oo]);
                float e[10];
                float sum = 0.f;
                #pragma unroll
                for (int oo = 0; oo < 10; oo++) { e[oo] = __expf(lg[oo] - m); sum += e[oo]; }
                float inv = 1.f / sum;
                #pragma unroll
                for (int oo = 0; oo < 10; oo++)
                    s_probst[(s * 10 + oo) * 36 + i] = e[oo] * inv;
            }
            __syncthreads();
        }

        // weighted sum over i + squash over d. 320 tasks (10 whole warps);
        // 8-lane shfl groups each hold one (s,o) with 2 d per lane.
        if (tid < NS * 80) {
            const __half2* pr = ph + s_ws * 36 * HP2PITCH + od2_ws;
            float acc0 = 0.f, acc1 = 0.f;
            if (it == 0) {
                #pragma unroll 4
                for (int i = 0; i < 36; i++) {
                    float2 p = __half22float2(pr[i * HP2PITCH]);
                    acc0 += p.x; acc1 += p.y;
                }
                acc0 *= 0.1f; acc1 *= 0.1f;    // softmax(0) over 10 classes
            } else {
                const float4* pb4 = (const float4*)&s_probst[(s_ws * 10 + o_ws) * 36];
                #pragma unroll
                for (int ii = 0; ii < 9; ii++) {
                    float4 pv = pb4[ii];
                    float2 p0 = __half22float2(pr[(4 * ii + 0) * HP2PITCH]);
                    float2 p1 = __half22float2(pr[(4 * ii + 1) * HP2PITCH]);
                    float2 p2 = __half22float2(pr[(4 * ii + 2) * HP2PITCH]);
                    float2 p3 = __half22float2(pr[(4 * ii + 3) * HP2PITCH]);
                    acc0 = fmaf(pv.x, p0.x, acc0); acc1 = fmaf(pv.x, p0.y, acc1);
                    acc0 = fmaf(pv.y, p1.x, acc0); acc1 = fmaf(pv.y, p1.y, acc1);
                    acc0 = fmaf(pv.z, p2.x, acc0); acc1 = fmaf(pv.z, p2.y, acc1);
                    acc0 = fmaf(pv.w, p3.x, acc0); acc1 = fmaf(pv.w, p3.y, acc1);
                }
            }
            float n2 = fmaf(acc0, acc0, acc1 * acc1);
            n2 += __shfl_xor_sync(FULL, n2, 1);
            n2 += __shfl_xor_sync(FULL, n2, 2);
            n2 += __shfl_xor_sync(FULL, n2, 4);
            float f = n2 / (1.f + n2) * rsqrtf(n2 + 1e-8f);
            out0 = acc0 * f;
            out1 = acc1 * f;
            if (it < 2)
                ((float2*)s_out)[s_ws * 80 + od2_ws] = make_float2(out0, out1);
        }

        if (it == 2) break;
        __syncthreads();               // s_out published

        // agreement: logits[s][i][o] (+)= sum_d priors*out, priors as 2x uint4
        for (int t = tid; t < NS * 360; t += NTHR) {
            int s = t / 360;
            int r = t % 360;
            int oo = r / 36;
            int i = r % 36;
            const uint4* pr4 = (const uint4*)(ph + (s * 36 + i) * HP2PITCH + oo * 8);
            uint4 A = pr4[0], B = pr4[1];
            const float4* ov4 = (const float4*)&s_out[s * 160 + oo * 16];
            float4 q0 = ov4[0], q1 = ov4[1], q2 = ov4[2], q3 = ov4[3];
            float sum = 0.f;
            float2 p;
            p = __half22float2(*(__half2*)&A.x); sum = fmaf(p.x, q0.x, sum); sum = fmaf(p.y, q0.y, sum);
            p = __half22float2(*(__half2*)&A.y); sum = fmaf(p.x, q0.z, sum); sum = fmaf(p.y, q0.w, sum);
            p = __half22float2(*(__half2*)&A.z); sum = fmaf(p.x, q1.x, sum); sum = fmaf(p.y, q1.y, sum);
            p = __half22float2(*(__half2*)&A.w); sum = fmaf(p.x, q1.z, sum); sum = fmaf(p.y, q1.w, sum);
            p = __half22float2(*(__half2*)&B.x); sum = fmaf(p.x, q2.x, sum); sum = fmaf(p.y, q2.y, sum);
            p = __half22float2(*(__half2*)&B.y); sum = fmaf(p.x, q2.z, sum); sum = fmaf(p.y, q2.w, sum);
            p = __half22float2(*(__half2*)&B.z); sum = fmaf(p.x, q3.x, sum); sum = fmaf(p.y, q3.y, sum);
            p = __half22float2(*(__half2*)&B.w); sum = fmaf(p.x, q3.z, sum); sum = fmaf(p.y, q3.w, sum);
            float* lp = &s_logit[(s * 36 + i) * LPITCH + oo];
            if (it == 0) *lp = sum;    // initial logits are zero
            else         *lp += sum;
        }
        // loop-top syncthreads orders agreement -> softmax
    }

    // ---- write output (float2, coalesced) ----
    if (tid < NS * 80)
        ((float2*)out_g)[(sample0 + s_ws) * 80 + od2_ws] = make_float2(out0, out1);
}

extern "C" void kernel_launch(void* const* d_in, const int* in_sizes, int n_in,
                              void* d_out, int out_size) {
    const float* x      = (const float*)d_in[0];
    const float* conv_w = (const float*)d_in[1];
    const float* lin_w  = (const float*)d_in[2];
    float* out = (float*)d_out;

    transpose_w_kernel<<<(46080 + 255) / 256, 256>>>(lin_w);

    size_t smem_f = (size_t)NS * 36 * HP2PITCH + NS * 36 * 8
                  + (size_t)NS * 360 + NS * 160
                  + (size_t)NS * 36 * LPITCH + NS * 9 + 288;
    size_t smem_bytes = smem_f * sizeof(float);   // 68,944 B -> 3 CTAs/SM
    cudaFuncSetAttribute(capsnet_kernel,
                         cudaFuncAttributeMaxDynamicSharedMemorySize,
                         (int)smem_bytes);

    int blocks = 16384 / NS;   // 4096
    capsnet_kernel<<<blocks, NTHR, smem_bytes>>>(x, conv_w, out);
}

// round 15
// speedup vs baseline: 1.9188x; 1.0022x over previous
#include <cuda_runtime.h>
#include <cuda_fp16.h>

// ---------------------------------------------------------------------------
// CapsNet forward, fully fused. HFMA2-priors + vectorized-ws edition.
//   conv(3x3,pad1) -> squash(8) -> priors einsum -> 3-iter dynamic routing
// Inputs: x[16384,1,3,3] f32, conv_w[32,1,3,3] f32, lin_w[10,36,16,8] f32.
// Output: [16384,10,16] f32.
//
// vs R13: the weighted-sum (ws) pass is re-shaped from task=(s,od2) scalar
// LDS (lane stride 84 words -> 4-way bank conflict, 4 wf per 128B) to
// task=(s,o,dquad): 160 threads, each owns 4 d and reads priors as
// conflict-free LDS.64 of consecutive 8B chunks. ws priors wavefronts
// 4320 -> 1080 per block (the largest single L1 item). Per-d accumulation
// order unchanged -> bitwise-identical results.
// 640 threads, __launch_bounds__(640,3), smem 68,944 B -> 3 CTAs/SM.
// (Resubmission - R14 hit GPUAcquisitionTimeout; this kernel has never run.)
// ---------------------------------------------------------------------------

#define NS 4
#define HP2PITCH 84         // half2 units per prior row (80 data + 4 pad)
#define LPITCH 11           // logits pitch (gcd(11,32)=1)
#define NTHR 640

__device__ __half g_wt_h[36 * 80 * 16];   // [i][od2][l][odp]: half2 = (w_e, w_o)

__global__ void transpose_w_kernel(const float* __restrict__ lin_w) {
    int t = blockIdx.x * 256 + threadIdx.x;
    if (t >= 46080) return;
    int odp = t & 1;
    int l   = (t >> 1) & 7;
    int od2 = (t >> 4) % 80;
    int i   = t / 1280;
    int od  = od2 * 2 + odp;
    int o   = od / 16;
    int d   = od % 16;
    g_wt_h[t] = __float2half(lin_w[((o * 36 + i) * 16 + d) * 8 + l]);
}

__global__ __launch_bounds__(NTHR, 3)
void capsnet_kernel(const float* __restrict__ x,
                    const float* __restrict__ conv_w,
                    float* __restrict__ out_g) {
    extern __shared__ float sm[];
    __half2* ph     = (__half2*)sm;                     // 4*36*84 h2
    float* s_caps   = sm + NS * 36 * HP2PITCH;          // 1152 f
    float* s_probst = s_caps + NS * 36 * 8;             // 1440 f
    float* s_out    = s_probst + NS * 360;              // 640 f
    float* s_logit  = s_out + NS * 160;                 // 1584 f
    float* s_x      = s_logit + NS * 36 * LPITCH;       // 36 f
    float* s_cw     = s_x + NS * 9;                     // 288 f
    // total = 17236 floats = 68,944 B

    const int tid = threadIdx.x;
    const int sample0 = blockIdx.x * NS;

    // ---- load inputs ----
    if (tid < NS * 9)  s_x[tid]  = x[sample0 * 9 + tid];
    else if (tid >= 64 && tid < 64 + 288) s_cw[tid - 64] = conv_w[tid - 64];
    __syncthreads();

    // ---- conv 3x3 pad1 on 3x3 input, into capsule layout (fp32) ----
    for (int idx = tid; idx < NS * 288; idx += NTHR) {
        int s = idx / 288, r = idx % 288;
        int c = r / 9, p = r % 9;
        int h = p / 3, w = p % 3;
        float acc = 0.f;
        #pragma unroll
        for (int kh = 0; kh < 3; kh++) {
            int ih = h + kh - 1;
            if (ih < 0 || ih > 2) continue;
            #pragma unroll
            for (int kw = 0; kw < 3; kw++) {
                int iw = w + kw - 1;
                if (iw < 0 || iw > 2) continue;
                acc = fmaf(s_x[s * 9 + ih * 3 + iw], s_cw[c * 9 + kh * 3 + kw], acc);
            }
        }
        int g = c >> 3, l = c & 7;
        int i = p * 4 + g;
        s_caps[(s * 36 + i) * 8 + l] = acc;
    }
    __syncthreads();

    // ---- squash over length 8; write back IN-PLACE as duplicated half2 ----
    if (tid < NS * 36) {
        float* cp = &s_caps[tid * 8];
        float v[8];
        float n2 = 0.f;
        #pragma unroll
        for (int l = 0; l < 8; l++) { v[l] = cp[l]; n2 = fmaf(v[l], v[l], n2); }
        float f = n2 / (1.f + n2) * rsqrtf(n2 + 1e-8f);
        __half2* cph = (__half2*)cp;   // same 32B row, same thread: no hazard
        #pragma unroll
        for (int l = 0; l < 8; l++) cph[l] = __float2half2_rn(v[l] * f);
    }
    __syncthreads();

    // ---- priors via HFMA2: thread owns fixed od2; i strides by 8 ----
    // w[l] = (w_even, w_odd); c[l] = (c,c) dup  =>  hfma2 lane0->od_e, lane1->od_o
    {
        const int od2 = tid % 80;
        for (int i = tid / 80; i < 36; i += 8) {
            const uint4* wp = (const uint4*)(g_wt_h + (size_t)(i * 80 + od2) * 16);
            uint4 W0 = wp[0];          // l = 0..3 pairs
            uint4 W1 = wp[1];          // l = 4..7 pairs
            const __half2* w03 = (const __half2*)&W0;
            const __half2* w47 = (const __half2*)&W1;
            #pragma unroll
            for (int s = 0; s < NS; s++) {
                const uint4* cp = (const uint4*)&s_caps[(s * 36 + i) * 8];
                uint4 C0 = cp[0], C1 = cp[1];
                const __half2* c03 = (const __half2*)&C0;
                const __half2* c47 = (const __half2*)&C1;
                __half2 a = __hmul2(w03[0], c03[0]);
                a = __hfma2(w03[1], c03[1], a);
                a = __hfma2(w03[2], c03[2], a);
                a = __hfma2(w03[3], c03[3], a);
                __half2 b = __hmul2(w47[0], c47[0]);
                b = __hfma2(w47[1], c47[1], b);
                b = __hfma2(w47[2], c47[2], b);
                b = __hfma2(w47[3], c47[3], b);
                ph[(s * 36 + i) * HP2PITCH + od2] = __hadd2(a, b);
            }
        }
    }
    __syncthreads();

    // ---- dynamic routing (3 iterations) ----
    // ws task = (s, o, dq): 160 threads, 4 d each. Conflict-free LDS.64:
    // lanes read consecutive 8B chunks of a prior row.
    const unsigned FULL = 0xffffffffu;
    float o0 = 0.f, o1 = 0.f, o2 = 0.f, o3 = 0.f;
    const int s_ws  = tid / 40;        // ws task decode (valid for tid < 160)
    const int r_ws  = tid % 40;
    const int o_ws  = r_ws / 4;
    const int dq_ws = r_ws % 4;

    for (int it = 0; it < 3; it++) {
        if (it > 0) {
            __syncthreads();           // agreement wrote s_logit
            if (tid < NS * 36) {       // softmax over o -> probs_t[s][o][i]
                const int s = tid / 36, i = tid % 36;
                const float* lg = &s_logit[tid * LPITCH];
                float m = lg[0];
                #pragma unroll
                for (int oo = 1; oo < 10; oo++) m = fmaxf(m, lg[oo]);
                float e[10];
                float sum = 0.f;
                #pragma unroll
                for (int oo = 0; oo < 10; oo++) { e[oo] = __expf(lg[oo] - m); sum += e[oo]; }
                float inv = 1.f / sum;
                #pragma unroll
                for (int oo = 0; oo < 10; oo++)
                    s_probst[(s * 10 + oo) * 36 + i] = e[oo] * inv;
            }
            __syncthreads();
        }

        if (tid < NS * 40) {
            // base: prior row for (s_ws, i=0) at half2 offset o*8 + dq*2
            const __half2* prb = ph + s_ws * 36 * HP2PITCH + o_ws * 8 + dq_ws * 2;
            float a0 = 0.f, a1 = 0.f, a2 = 0.f, a3 = 0.f;
            if (it == 0) {
                #pragma unroll 4
                for (int i = 0; i < 36; i++) {
                    uint2 u = *(const uint2*)(prb + i * HP2PITCH);
                    float2 p0 = __half22float2(*(const __half2*)&u.x);
                    float2 p1 = __half22float2(*(const __half2*)&u.y);
                    a0 += p0.x; a1 += p0.y; a2 += p1.x; a3 += p1.y;
                }
                a0 *= 0.1f; a1 *= 0.1f; a2 *= 0.1f; a3 *= 0.1f;
            } else {
                const float4* pb4 = (const float4*)&s_probst[(s_ws * 10 + o_ws) * 36];
                #pragma unroll 3
                for (int ii = 0; ii < 9; ii++) {
                    float4 pv = pb4[ii];
                    #pragma unroll
                    for (int k = 0; k < 4; k++) {
                        float w = (k == 0) ? pv.x : (k == 1) ? pv.y : (k == 2) ? pv.z : pv.w;
                        uint2 u = *(const uint2*)(prb + (4 * ii + k) * HP2PITCH);
                        float2 p0 = __half22float2(*(const __half2*)&u.x);
                        float2 p1 = __half22float2(*(const __half2*)&u.y);
                        a0 = fmaf(w, p0.x, a0);
                        a1 = fmaf(w, p0.y, a1);
                        a2 = fmaf(w, p1.x, a2);
                        a3 = fmaf(w, p1.y, a3);
                    }
                }
            }
            // squash over 16 d: partial over 4 d, then sum across the 4-lane
            // (s,o) group (groups are 4-aligned -> never cross a warp).
            float n2 = fmaf(a0, a0, fmaf(a1, a1, fmaf(a2, a2, a3 * a3)));
            n2 += __shfl_xor_sync(FULL, n2, 1);
            n2 += __shfl_xor_sync(FULL, n2, 2);
            float f = n2 / (1.f + n2) * rsqrtf(n2 + 1e-8f);
            o0 = a0 * f; o1 = a1 * f; o2 = a2 * f; o3 = a3 * f;
            if (it < 2)
                ((float4*)s_out)[s_ws * 40 + o_ws * 4 + dq_ws] =
                    make_float4(o0, o1, o2, o3);
        }

        if (it == 2) break;
        __syncthreads();               // s_out published

        // agreement: logits[s][i][o] (+)= sum_d priors*out, priors as 2x uint4
        // (uint4 lane pattern tiles all 32 banks per 8-lane phase: optimal)
        for (int t = tid; t < NS * 360; t += NTHR) {
            int s = t / 360;
            int r = t % 360;
            int oo = r / 36;
            int i = r % 36;
            const uint4* pr4 = (const uint4*)(ph + (s * 36 + i) * HP2PITCH + oo * 8);
            uint4 A = pr4[0], B = pr4[1];
            const float4* ov4 = (const float4*)&s_out[s * 160 + oo * 16];
            float4 q0 = ov4[0], q1 = ov4[1], q2 = ov4[2], q3 = ov4[3];
            float sum = 0.f;
            float2 p;
            p = __half22float2(*(__half2*)&A.x); sum = fmaf(p.x, q0.x, sum); sum = fmaf(p.y, q0.y, sum);
            p = __half22float2(*(__half2*)&A.y); sum = fmaf(p.x, q0.z, sum); sum = fmaf(p.y, q0.w, sum);
            p = __half22float2(*(__half2*)&A.z); sum = fmaf(p.x, q1.x, sum); sum = fmaf(p.y, q1.y, sum);
            p = __half22float2(*(__half2*)&A.w); sum = fmaf(p.x, q1.z, sum); sum = fmaf(p.y, q1.w, sum);
            p = __half22float2(*(__half2*)&B.x); sum = fmaf(p.x, q2.x, sum); sum = fmaf(p.y, q2.y, sum);
            p = __half22float2(*(__half2*)&B.y); sum = fmaf(p.x, q2.z, sum); sum = fmaf(p.y, q2.w, sum);
            p = __half22float2(*(__half2*)&B.z); sum = fmaf(p.x, q3.x, sum); sum = fmaf(p.y, q3.y, sum);
            p = __half22float2(*(__half2*)&B.w); sum = fmaf(p.x, q3.z, sum); sum = fmaf(p.y, q3.w, sum);
            float* lp = &s_logit[(s * 36 + i) * LPITCH + oo];
            if (it == 0) *lp = sum;    // initial logits are zero
            else         *lp += sum;
        }
        // loop-top syncthreads orders agreement -> softmax
    }

    // ---- write output (float4, coalesced) ----
    if (tid < NS * 40)
        ((float4*)out_g)[(sample0 + s_ws) * 40 + o_ws * 4 + dq_ws] =
            make_float4(o0, o1, o2, o3);
}

extern "C" void kernel_launch(void* const* d_in, const int* in_sizes, int n_in,
                              void* d_out, int out_size) {
    const float* x      = (const float*)d_in[0];
    const float* conv_w = (const float*)d_in[1];
    const float* lin_w  = (const float*)d_in[2];
    float* out = (float*)d_out;

    transpose_w_kernel<<<(46080 + 255) / 256, 256>>>(lin_w);

    size_t smem_f = (size_t)NS * 36 * HP2PITCH + NS * 36 * 8
                  + (size_t)NS * 360 + NS * 160
                  + (size_t)NS * 36 * LPITCH + NS * 9 + 288;
    size_t smem_bytes = smem_f * sizeof(float);   // 68,944 B -> 3 CTAs/SM
    cudaFuncSetAttribute(capsnet_kernel,
                         cudaFuncAttributeMaxDynamicSharedMemorySize,
                         (int)smem_bytes);

    int blocks = 16384 / NS;   // 4096
    capsnet_kernel<<<blocks, NTHR, smem_bytes>>>(x, conv_w, out);
}